// round 8
// baseline (speedup 1.0000x reference)
#include <cuda_runtime.h>
#include <cuda_bf16.h>
#include <cstdint>

// Problem dims
#define Vv 32000
#define Ee 512
#define Hh 512
#define Bb 16
#define Ss 128
#define H4 (4*Hh)       // 2048
#define MROWS (Ss*Bb)   // 2048

// -------- device scratch (no allocation allowed) --------
__device__ float g_x0[MROWS * Ee];
__device__ float g_x1[MROWS * 2 * Hh];
__device__ float g_x2[MROWS * 2 * Hh];
__device__ float g_xg_f[MROWS * H4];
__device__ float g_xg_b[MROWS * H4];
__device__ float g_h[2 * 2 * Bb * Hh];
__device__ float g_c[2 * Bb * Hh];
// tf32-rounded weight copies (so GEMM needs no inner-loop cvt)
__device__ float g_linw[(size_t)Vv * 1024];   // 131MB
__device__ float g_w0f[H4 * Ee];
__device__ float g_w0b[H4 * Ee];
__device__ float g_w1f[H4 * 1024];
__device__ float g_w1b[H4 * 1024];

// ---------------- helpers ----------------
__device__ __forceinline__ float rtf(float f) {
    uint32_t r;
    asm("cvt.rna.tf32.f32 %0, %1;" : "=r"(r) : "f"(f));
    return __uint_as_float(r);
}
__device__ __forceinline__ uint32_t smem_u32(const void* p) {
    return (uint32_t)__cvta_generic_to_shared(p);
}
__device__ __forceinline__ void cp16(uint32_t dst, const void* src) {
    asm volatile("cp.async.cg.shared.global [%0], [%1], 16;" :: "r"(dst), "l"(src));
}
__device__ __forceinline__ void ldsm_x4(uint32_t* r, uint32_t addr) {
    asm volatile("ldmatrix.sync.aligned.m8n8.x4.shared.b16 {%0,%1,%2,%3}, [%4];"
                 : "=r"(r[0]), "=r"(r[1]), "=r"(r[2]), "=r"(r[3]) : "r"(addr));
}
__device__ __forceinline__ void ldsm_x2(uint32_t* r, uint32_t addr) {
    asm volatile("ldmatrix.sync.aligned.m8n8.x2.shared.b16 {%0,%1}, [%2];"
                 : "=r"(r[0]), "=r"(r[1]) : "r"(addr));
}
__device__ __forceinline__ void mma_tf32(float* c, const uint32_t* a, const uint32_t* b) {
    asm volatile(
        "mma.sync.aligned.m16n8k8.row.col.f32.tf32.tf32.f32 "
        "{%0,%1,%2,%3}, {%4,%5,%6,%7}, {%8,%9}, {%0,%1,%2,%3};"
        : "+f"(c[0]), "+f"(c[1]), "+f"(c[2]), "+f"(c[3])
        : "r"(a[0]), "r"(a[1]), "r"(a[2]), "r"(a[3]), "r"(b[0]), "r"(b[1]));
}

// ---------------- small kernels ----------------
__global__ void round_copy(const float* __restrict__ s, float* __restrict__ d, int n4) {
    int i = blockIdx.x * 256 + threadIdx.x;
    if (i < n4) {
        float4 v = ((const float4*)s)[i];
        v.x = rtf(v.x); v.y = rtf(v.y); v.z = rtf(v.z); v.w = rtf(v.w);
        ((float4*)d)[i] = v;
    }
}

__global__ void embed_kernel(const int* __restrict__ idx,
                             const float* __restrict__ ew) {
    int sb = blockIdx.x;
    int s = sb >> 4, b = sb & 15;
    int token = idx[b * Ss + s];
    const float4* src = (const float4*)(ew + (size_t)token * Ee);
    float4* dst = (float4*)(g_x0 + ((size_t)s * Bb + b) * Ee);
    float4 v = src[threadIdx.x];
    v.x = rtf(v.x); v.y = rtf(v.y); v.z = rtf(v.z); v.w = rtf(v.w);
    dst[threadIdx.x] = v;
}

__global__ void zero_state() {
    int i = blockIdx.x * 256 + threadIdx.x;
    if (i < 2 * Bb * Hh) {
        g_h[i] = 0.f;
        g_c[i] = 0.f;
    }
}

// ============================================================
// TF32 tensor-core GEMM (NT): C = A[M,K] . B[N,K]^T (+bias)
// BM=BN=128, BK=32, 256 threads = 8 warps, warp tile 64x32.
// ldmatrix fragment loads (operands pre-rounded to tf32-RNA).
// 2-stage cp.async pipeline. Row pitch 44 floats (176B):
// 16B-aligned ldmatrix rows, stride 12 words mod 32 -> conflict-free.
// mode 0: C[m*N+n] = acc + b1[n] + b2[n]
// mode 1: out[((m&15)*V + n)*S + (m>>4)] = acc + b1[n]
// ============================================================
#define BKP 44
#define TILE_B (128 * BKP * 4)       // 22528 bytes per tile per stage
#define SM_A(st) ((st) * TILE_B)
#define SM_B(st) (2 * TILE_B + (st) * TILE_B)
#define SMEM_GEMM (4 * TILE_B)       // 90112 bytes

__global__ __launch_bounds__(256, 2)
void tf32_gemm(const float* __restrict__ A, const float* __restrict__ Bw,
               const float* __restrict__ b1, const float* __restrict__ b2,
               float* __restrict__ C, int M, int N, int K, int mode) {
    extern __shared__ float smem[];
    const int tid = threadIdx.x;
    const int lane = tid & 31, wid = tid >> 5;
    const int gid = lane >> 2, tig = lane & 3;
    const int wm = (wid & 1) * 64;        // warp m offset
    const int wn = (wid >> 1) * 32;       // warp n offset
    const int bm = blockIdx.x * 128, bn = blockIdx.y * 128;
    uint32_t s_base = smem_u32(smem);

    // ldmatrix lane geometry
    const int q = lane >> 3, rr = lane & 7;
    const int a_row = wm + (q & 1) * 8 + rr;   // + mt*16
    const int a_chunk = (q >> 1) * 4;          // k sub-chunk (0 or 4)
    const int b_row = wn + rr;                 // + nt*8
    const int b_chunk = (q & 1) * 4;

    float acc[4][4][4];
    #pragma unroll
    for (int i = 0; i < 4; i++)
        #pragma unroll
        for (int j = 0; j < 4; j++)
            #pragma unroll
            for (int e = 0; e < 4; e++) acc[i][j][e] = 0.f;

    const int NT = K >> 5;

    auto load_tiles = [&](int st, int kof) {
        #pragma unroll
        for (int i = 0; i < 4; i++) {
            int id = tid + i * 256;
            int r = id >> 3, c4 = id & 7;
            cp16(s_base + SM_A(st) + (uint32_t)((r * BKP + c4 * 4) * 4),
                 A + (size_t)(bm + r) * K + kof + c4 * 4);
            cp16(s_base + SM_B(st) + (uint32_t)((r * BKP + c4 * 4) * 4),
                 Bw + (size_t)(bn + r) * K + kof + c4 * 4);
        }
        asm volatile("cp.async.commit_group;");
    };

    load_tiles(0, 0);

    for (int kt = 0; kt < NT; kt++) {
        if (kt + 1 < NT) {
            load_tiles((kt + 1) & 1, (kt + 1) * 32);
            asm volatile("cp.async.wait_group 1;");
        } else {
            asm volatile("cp.async.wait_group 0;");
        }
        __syncthreads();

        const uint32_t aS = s_base + SM_A(kt & 1);
        const uint32_t bS = s_base + SM_B(kt & 1);

        #pragma unroll
        for (int ks = 0; ks < 4; ks++) {
            const int k0 = ks * 8;
            uint32_t af[4][4], bf[4][2];
            #pragma unroll
            for (int mt = 0; mt < 4; mt++)
                ldsm_x4(af[mt],
                        aS + (uint32_t)((((a_row + mt * 16) * BKP) + k0 + a_chunk) * 4));
            #pragma unroll
            for (int nt = 0; nt < 4; nt++)
                ldsm_x2(bf[nt],
                        bS + (uint32_t)((((b_row + nt * 8) * BKP) + k0 + b_chunk) * 4));
            #pragma unroll
            for (int mt = 0; mt < 4; mt++)
                #pragma unroll
                for (int nt = 0; nt < 4; nt++)
                    mma_tf32(acc[mt][nt], af[mt], bf[nt]);
        }
        __syncthreads();
    }

    // -------- epilogue --------
    #pragma unroll
    for (int mt = 0; mt < 4; mt++) {
        int m0 = bm + wm + mt * 16 + gid;   // rows m0 and m0+8
        #pragma unroll
        for (int nt = 0; nt < 4; nt++) {
            int n = bn + wn + nt * 8 + tig * 2;   // cols n, n+1
            float* a = acc[mt][nt];
            if (mode == 0) {
                float bb0 = b1[n] + b2[n];
                float bb1 = b1[n + 1] + b2[n + 1];
                *(float2*)(C + (size_t)m0 * N + n) = make_float2(a[0] + bb0, a[1] + bb1);
                *(float2*)(C + (size_t)(m0 + 8) * N + n) = make_float2(a[2] + bb0, a[3] + bb1);
            } else {
                float bb0 = b1[n], bb1 = b1[n + 1];
                int s0 = m0 >> 4, b0 = m0 & 15;
                int s1 = (m0 + 8) >> 4, b1i = (m0 + 8) & 15;
                C[((size_t)b0 * Vv + n) * Ss + s0]       = a[0] + bb0;
                C[((size_t)b0 * Vv + n + 1) * Ss + s0]   = a[1] + bb1;
                C[((size_t)b1i * Vv + n) * Ss + s1]      = a[2] + bb0;
                C[((size_t)b1i * Vv + n + 1) * Ss + s1]  = a[3] + bb1;
            }
        }
    }
}

// -------- fused LSTM step: both directions, one time step --------
__global__ __launch_bounds__(128)
void lstm_step(const float* __restrict__ xg_f, const float* __restrict__ xg_b,
               const float* __restrict__ Whh_f, const float* __restrict__ Whh_b,
               float* __restrict__ xnext, int t) {
    __shared__ float hs[Hh * 17];

    int dir = blockIdx.x & 1;
    int jblk = blockIdx.x >> 1;
    int tid = threadIdx.x;
    int b = tid & 15, jl = tid >> 4;
    int j = jblk * 8 + jl;

    const float* Whh = dir ? Whh_b : Whh_f;
    const float* xg = dir ? xg_b : xg_f;
    int tt = dir ? (Ss - 1 - t) : t;

    const float* hread = g_h + (size_t)(t & 1) * (2 * Bb * Hh) + (size_t)dir * (Bb * Hh);
    float* hwrite = g_h + (size_t)((t + 1) & 1) * (2 * Bb * Hh) + (size_t)dir * (Bb * Hh);
    float* cstate = g_c + (size_t)dir * (Bb * Hh);

    for (int idx = tid; idx < Bb * Hh; idx += 128) {
        int bb = idx >> 9;
        int kk = idx & 511;
        hs[kk * 17 + bb] = hread[idx];
    }
    __syncthreads();

    const float4* wi = (const float4*)(Whh + (size_t)(0 * Hh + j) * Hh);
    const float4* wf = (const float4*)(Whh + (size_t)(1 * Hh + j) * Hh);
    const float4* wg = (const float4*)(Whh + (size_t)(2 * Hh + j) * Hh);
    const float4* wo = (const float4*)(Whh + (size_t)(3 * Hh + j) * Hh);

    float ai = 0.f, af = 0.f, ag = 0.f, ao = 0.f;
    #pragma unroll 4
    for (int k4 = 0; k4 < Hh / 4; k4++) {
        float4 vi = __ldg(wi + k4);
        float4 vf = __ldg(wf + k4);
        float4 vg = __ldg(wg + k4);
        float4 vo = __ldg(wo + k4);
        int k = k4 * 4;
        float h0 = hs[(k + 0) * 17 + b];
        float h1 = hs[(k + 1) * 17 + b];
        float h2 = hs[(k + 2) * 17 + b];
        float h3 = hs[(k + 3) * 17 + b];
        ai += vi.x * h0 + vi.y * h1 + vi.z * h2 + vi.w * h3;
        af += vf.x * h0 + vf.y * h1 + vf.z * h2 + vf.w * h3;
        ag += vg.x * h0 + vg.y * h1 + vg.z * h2 + vg.w * h3;
        ao += vo.x * h0 + vo.y * h1 + vo.z * h2 + vo.w * h3;
    }

    size_t base = ((size_t)tt * Bb + b) * (size_t)H4;
    ai += xg[base + 0 * Hh + j];
    af += xg[base + 1 * Hh + j];
    ag += xg[base + 2 * Hh + j];
    ao += xg[base + 3 * Hh + j];

    float ii = 1.f / (1.f + __expf(-ai));
    float ff = 1.f / (1.f + __expf(-af));
    float gg = tanhf(ag);
    float oo = 1.f / (1.f + __expf(-ao));

    int sidx = b * Hh + j;
    float c = ff * cstate[sidx] + ii * gg;
    float h = oo * tanhf(c);
    cstate[sidx] = c;
    hwrite[sidx] = h;
    // GEMM input gets tf32-rounded value (recurrence keeps full precision)
    xnext[((size_t)tt * Bb + b) * (size_t)(2 * Hh) + (size_t)dir * Hh + j] = rtf(h);
}

// ---------------- host launcher ----------------
extern "C" void kernel_launch(void* const* d_in, const int* in_sizes, int n_in,
                              void* d_out, int out_size) {
    const int* input = (const int*)d_in[0];
    const float* embed_w = (const float*)d_in[1];
    const float* Wih[2][2]; const float* Whh[2][2];
    const float* bih[2][2]; const float* bhh[2][2];
    int p = 2;
    for (int l = 0; l < 2; l++) {
        for (int d = 0; d < 2; d++) {
            Wih[l][d] = (const float*)d_in[p++];
            Whh[l][d] = (const float*)d_in[p++];
            bih[l][d] = (const float*)d_in[p++];
            bhh[l][d] = (const float*)d_in[p++];
        }
    }
    const float* lin_w = (const float*)d_in[18];
    const float* lin_b = (const float*)d_in[19];
    float* out = (float*)d_out;

    float *x0p, *x1p, *x2p, *xgf, *xgb, *lwp, *w0f, *w0b, *w1f, *w1b;
    cudaGetSymbolAddress((void**)&x0p, g_x0);
    cudaGetSymbolAddress((void**)&x1p, g_x1);
    cudaGetSymbolAddress((void**)&x2p, g_x2);
    cudaGetSymbolAddress((void**)&xgf, g_xg_f);
    cudaGetSymbolAddress((void**)&xgb, g_xg_b);
    cudaGetSymbolAddress((void**)&lwp, g_linw);
    cudaGetSymbolAddress((void**)&w0f, g_w0f);
    cudaGetSymbolAddress((void**)&w0b, g_w0b);
    cudaGetSymbolAddress((void**)&w1f, g_w1f);
    cudaGetSymbolAddress((void**)&w1b, g_w1b);

    cudaFuncSetAttribute(tf32_gemm, cudaFuncAttributeMaxDynamicSharedMemorySize,
                         SMEM_GEMM);

    // 0) round weights to tf32 (RNA) into scratch
    {
        int n4 = (Vv * 1024) / 4;
        round_copy<<<(n4 + 255) / 256, 256>>>(lin_w, lwp, n4);
        n4 = (H4 * Ee) / 4;
        round_copy<<<(n4 + 255) / 256, 256>>>(Wih[0][0], w0f, n4);
        round_copy<<<(n4 + 255) / 256, 256>>>(Wih[0][1], w0b, n4);
        n4 = (H4 * 1024) / 4;
        round_copy<<<(n4 + 255) / 256, 256>>>(Wih[1][0], w1f, n4);
        round_copy<<<(n4 + 255) / 256, 256>>>(Wih[1][1], w1b, n4);
    }

    // 1) embedding (rounded)
    embed_kernel<<<MROWS, 128>>>(input, embed_w);

    const float* xin = x0p;
    float* xouts[2] = {x1p, x2p};
    const float* wih_r[2][2] = {{w0f, w0b}, {w1f, w1b}};
    int kdims[2] = {Ee, 2 * Hh};

    for (int l = 0; l < 2; l++) {
        int K = kdims[l];
        dim3 ggrid(MROWS / 128, H4 / 128);   // (16, 16)
        tf32_gemm<<<ggrid, 256, SMEM_GEMM>>>(xin, wih_r[l][0], bih[l][0], bhh[l][0],
                                             xgf, MROWS, H4, K, 0);
        tf32_gemm<<<ggrid, 256, SMEM_GEMM>>>(xin, wih_r[l][1], bih[l][1], bhh[l][1],
                                             xgb, MROWS, H4, K, 0);
        zero_state<<<64, 256>>>();
        for (int t = 0; t < Ss; t++) {
            lstm_step<<<128, 128>>>(xgf, xgb, Whh[l][0], Whh[l][1], xouts[l], t);
        }
        xin = xouts[l];
    }

    // 3) vocab projection with [B,V,S] scatter
    dim3 ogrid(MROWS / 128, Vv / 128);       // (16, 250), m fastest -> lin_w L2 reuse
    tf32_gemm<<<ogrid, 256, SMEM_GEMM>>>(x2p, lwp, lin_b, nullptr,
                                         out, MROWS, Vv, 2 * Hh, 1);
}

// round 9
// speedup vs baseline: 1.1605x; 1.1605x over previous
#include <cuda_runtime.h>
#include <cuda_bf16.h>
#include <cstdint>

// Problem dims
#define Vv 32000
#define Ee 512
#define Hh 512
#define Bb 16
#define Ss 128
#define H4 (4*Hh)       // 2048
#define MROWS (Ss*Bb)   // 2048

// -------- device scratch (no allocation allowed) --------
__device__ float g_x0[MROWS * Ee];
__device__ float g_x1[MROWS * 2 * Hh];
__device__ float g_x2[MROWS * 2 * Hh];
__device__ float g_xg_f[MROWS * H4];
__device__ float g_xg_b[MROWS * H4];
__device__ float g_h[2 * 2 * Bb * Hh];    // [parity][dir][b*H]
__device__ unsigned g_arrive;             // persistent-scan sync counter
// tf32-rounded weight copies (so GEMM needs no inner-loop cvt)
__device__ float g_linw[(size_t)Vv * 1024];   // 131MB
__device__ float g_w0f[H4 * Ee];
__device__ float g_w0b[H4 * Ee];
__device__ float g_w1f[H4 * 1024];
__device__ float g_w1b[H4 * 1024];

// ---------------- helpers ----------------
__device__ __forceinline__ float rtf(float f) {
    uint32_t r;
    asm("cvt.rna.tf32.f32 %0, %1;" : "=r"(r) : "f"(f));
    return __uint_as_float(r);
}
__device__ __forceinline__ uint32_t smem_u32(const void* p) {
    return (uint32_t)__cvta_generic_to_shared(p);
}
__device__ __forceinline__ void cp16(uint32_t dst, const void* src) {
    asm volatile("cp.async.cg.shared.global [%0], [%1], 16;" :: "r"(dst), "l"(src));
}
__device__ __forceinline__ void ldsm_x4(uint32_t* r, uint32_t addr) {
    asm volatile("ldmatrix.sync.aligned.m8n8.x4.shared.b16 {%0,%1,%2,%3}, [%4];"
                 : "=r"(r[0]), "=r"(r[1]), "=r"(r[2]), "=r"(r[3]) : "r"(addr));
}
__device__ __forceinline__ void ldsm_x2(uint32_t* r, uint32_t addr) {
    asm volatile("ldmatrix.sync.aligned.m8n8.x2.shared.b16 {%0,%1}, [%2];"
                 : "=r"(r[0]), "=r"(r[1]) : "r"(addr));
}
__device__ __forceinline__ void mma_tf32(float* c, const uint32_t* a, const uint32_t* b) {
    asm volatile(
        "mma.sync.aligned.m16n8k8.row.col.f32.tf32.tf32.f32 "
        "{%0,%1,%2,%3}, {%4,%5,%6,%7}, {%8,%9}, {%0,%1,%2,%3};"
        : "+f"(c[0]), "+f"(c[1]), "+f"(c[2]), "+f"(c[3])
        : "r"(a[0]), "r"(a[1]), "r"(a[2]), "r"(a[3]), "r"(b[0]), "r"(b[1]));
}

// ---------------- small kernels ----------------
__global__ void round_copy(const float* __restrict__ s, float* __restrict__ d, int n4) {
    int i = blockIdx.x * 256 + threadIdx.x;
    if (i < n4) {
        float4 v = ((const float4*)s)[i];
        v.x = rtf(v.x); v.y = rtf(v.y); v.z = rtf(v.z); v.w = rtf(v.w);
        ((float4*)d)[i] = v;
    }
}

__global__ void embed_kernel(const int* __restrict__ idx,
                             const float* __restrict__ ew) {
    int sb = blockIdx.x;
    int s = sb >> 4, b = sb & 15;
    int token = idx[b * Ss + s];
    const float4* src = (const float4*)(ew + (size_t)token * Ee);
    float4* dst = (float4*)(g_x0 + ((size_t)s * Bb + b) * Ee);
    float4 v = src[threadIdx.x];
    v.x = rtf(v.x); v.y = rtf(v.y); v.z = rtf(v.z); v.w = rtf(v.w);
    dst[threadIdx.x] = v;
}

__global__ void zero_state() {
    int i = blockIdx.x * 256 + threadIdx.x;
    if (i < 2 * Bb * Hh) g_h[i] = 0.f;    // parity-0 slab, both dirs
    if (i == 0) g_arrive = 0u;
}

// ============================================================
// TF32 tensor-core GEMM (NT): C = A[M,K] . B[N,K]^T (+bias)
// BM=BN=128, BK=32, 256 threads = 8 warps, warp tile 64x32.
// ldmatrix fragment loads (operands pre-rounded tf32-RNA).
// 4-stage cp.async ring, ONE __syncthreads per k-tile.
// mode 0: C[m*N+n] = acc + b1[n] + b2[n]
// mode 1: out[((m&15)*V + n)*S + (m>>4)] = acc + b1[n], smem-staged
//         so stores are float4-contiguous along s (no sector waste)
// ============================================================
#define BKP 44
#define TILE_B (128 * BKP * 4)       // 22528 bytes per stage
#define SM_A(st) ((st) * TILE_B)
#define SM_B(st) (4 * TILE_B + (st) * TILE_B)
#define SMEM_GEMM (8 * TILE_B)       // 180224 bytes... too big for 2 CTA; use 4+4 stages of A/B? no:
// NOTE: stages hold A and B together: layout below uses 4 stages x (A+B).
#undef SM_A
#undef SM_B
#define STAGE_B (2 * TILE_B)                  // A tile + B tile per stage? no — keep separate:
#undef STAGE_B
// Final layout: [A0..A3][B0..B3], total 8*22528 = 180224 -> exceeds 2-CTA budget.
// Use 4 stages but halve padding waste: keep 1 CTA/SM with 4 stages (180KB), deep
// pipeline substitutes for the second CTA's latency hiding.
#define SM_A2(st) ((st) * TILE_B)
#define SM_B2(st) (4 * TILE_B + (st) * TILE_B)
#define SMEM_GEMM_TOTAL (8 * TILE_B)

__global__ __launch_bounds__(256, 1)
void tf32_gemm(const float* __restrict__ A, const float* __restrict__ Bw,
               const float* __restrict__ b1, const float* __restrict__ b2,
               float* __restrict__ C, int M, int N, int K, int mode) {
    extern __shared__ float smem[];
    const int tid = threadIdx.x;
    const int lane = tid & 31, wid = tid >> 5;
    const int gid = lane >> 2, tig = lane & 3;
    const int wm = (wid & 1) * 64;        // warp m offset
    const int wn = (wid >> 1) * 32;       // warp n offset
    const int bm = blockIdx.x * 128, bn = blockIdx.y * 128;
    uint32_t s_base = smem_u32(smem);

    // ldmatrix lane geometry
    const int q = lane >> 3, rr = lane & 7;
    const int a_row = wm + (q & 1) * 8 + rr;
    const int a_chunk = (q >> 1) * 4;
    const int b_row = wn + rr;
    const int b_chunk = (q & 1) * 4;

    float acc[4][4][4];
    #pragma unroll
    for (int i = 0; i < 4; i++)
        #pragma unroll
        for (int j = 0; j < 4; j++)
            #pragma unroll
            for (int e = 0; e < 4; e++) acc[i][j][e] = 0.f;

    const int NT = K >> 5;

    auto load_tiles = [&](int kt, int st) {
        int kof = kt * 32;
        #pragma unroll
        for (int i = 0; i < 4; i++) {
            int id = tid + i * 256;
            int r = id >> 3, c4 = id & 7;
            cp16(s_base + SM_A2(st) + (uint32_t)((r * BKP + c4 * 4) * 4),
                 A + (size_t)(bm + r) * K + kof + c4 * 4);
            cp16(s_base + SM_B2(st) + (uint32_t)((r * BKP + c4 * 4) * 4),
                 Bw + (size_t)(bn + r) * K + kof + c4 * 4);
        }
        asm volatile("cp.async.commit_group;");
    };

    // prologue: stages 0,1,2
    load_tiles(0, 0);
    load_tiles(1, 1);
    load_tiles(2, 2);

    for (int kt = 0; kt < NT; kt++) {
        if (kt + 3 < NT) asm volatile("cp.async.wait_group 2;");
        else             asm volatile("cp.async.wait_group 0;");
        __syncthreads();
        if (kt + 3 < NT) load_tiles(kt + 3, (kt + 3) & 3);

        const uint32_t aS = s_base + SM_A2(kt & 3);
        const uint32_t bS = s_base + SM_B2(kt & 3);

        #pragma unroll
        for (int ks = 0; ks < 4; ks++) {
            const int k0 = ks * 8;
            uint32_t af[4][4], bf[4][2];
            #pragma unroll
            for (int mt = 0; mt < 4; mt++)
                ldsm_x4(af[mt],
                        aS + (uint32_t)((((a_row + mt * 16) * BKP) + k0 + a_chunk) * 4));
            #pragma unroll
            for (int nt = 0; nt < 4; nt++)
                ldsm_x2(bf[nt],
                        bS + (uint32_t)((((b_row + nt * 8) * BKP) + k0 + b_chunk) * 4));
            #pragma unroll
            for (int mt = 0; mt < 4; mt++)
                #pragma unroll
                for (int nt = 0; nt < 4; nt++)
                    mma_tf32(acc[mt][nt], af[mt], bf[nt]);
        }
    }

    if (mode == 0) {
        #pragma unroll
        for (int mt = 0; mt < 4; mt++) {
            int m0 = bm + wm + mt * 16 + gid;
            #pragma unroll
            for (int nt = 0; nt < 4; nt++) {
                int n = bn + wn + nt * 8 + tig * 2;
                float* a = acc[mt][nt];
                float bb0 = b1[n] + b2[n];
                float bb1 = b1[n + 1] + b2[n + 1];
                *(float2*)(C + (size_t)m0 * N + n) = make_float2(a[0] + bb0, a[1] + bb1);
                *(float2*)(C + (size_t)(m0 + 8) * N + n) = make_float2(a[2] + bb0, a[3] + bb1);
            }
        }
    } else {
        // stage C tile in smem, store coalesced along s
        __syncthreads();
        float* smc = smem;                   // [128][129]
        #pragma unroll
        for (int mt = 0; mt < 4; mt++) {
            int ml0 = wm + mt * 16 + gid;
            #pragma unroll
            for (int nt = 0; nt < 4; nt++) {
                int nl = wn + nt * 8 + tig * 2;
                float* a = acc[mt][nt];
                smc[ml0 * 129 + nl] = a[0];
                smc[ml0 * 129 + nl + 1] = a[1];
                smc[(ml0 + 8) * 129 + nl] = a[2];
                smc[(ml0 + 8) * 129 + nl + 1] = a[3];
            }
        }
        __syncthreads();
        int s_start = bm >> 4;               // bm multiple of 128
        int b = tid & 15;
        #pragma unroll 1
        for (int it = 0; it < 8; it++) {
            int vl = (tid >> 4) + it * 16;   // 0..127
            int v = bn + vl;
            float bias = b1[v];
            float vals[8];
            #pragma unroll
            for (int sl = 0; sl < 8; sl++)
                vals[sl] = smc[(sl * 16 + b) * 129 + vl] + bias;
            size_t o = ((size_t)b * Vv + v) * Ss + s_start;
            *(float4*)(C + o)     = make_float4(vals[0], vals[1], vals[2], vals[3]);
            *(float4*)(C + o + 4) = make_float4(vals[4], vals[5], vals[6], vals[7]);
        }
    }
}

// ============================================================
// Persistent bidirectional LSTM scan: ONE launch per layer.
// grid = 128 blocks (dir = bid&1, jblk = bid>>1), 128 threads (b, jl).
// c lives in a register; h exchanged via L2 (.cg) with counter grid-sync.
// Whh slice (64KB/block) stays L1-resident across all 128 steps.
// ============================================================
__global__ __launch_bounds__(128)
void lstm_scan(const float* __restrict__ xg_f, const float* __restrict__ xg_b,
               const float* __restrict__ Whh_f, const float* __restrict__ Whh_b,
               float* __restrict__ xnext) {
    __shared__ float hs[Hh * 17];

    const int dir = blockIdx.x & 1;
    const int jblk = blockIdx.x >> 1;
    const int tid = threadIdx.x;
    const int b = tid & 15, jl = tid >> 4;
    const int j = jblk * 8 + jl;
    const unsigned nb = gridDim.x;

    const float* Whh = dir ? Whh_b : Whh_f;
    const float* xg = dir ? xg_b : xg_f;

    const float4* wi = (const float4*)(Whh + (size_t)(0 * Hh + j) * Hh);
    const float4* wf = (const float4*)(Whh + (size_t)(1 * Hh + j) * Hh);
    const float4* wg = (const float4*)(Whh + (size_t)(2 * Hh + j) * Hh);
    const float4* wo = (const float4*)(Whh + (size_t)(3 * Hh + j) * Hh);

    unsigned* arr = &g_arrive;
    float c = 0.f;

    for (int t = 0; t < Ss; t++) {
        int tt = dir ? (Ss - 1 - t) : t;
        const float* hread = g_h + (size_t)(t & 1) * (2 * Bb * Hh) + (size_t)dir * (Bb * Hh);
        float* hwrite = g_h + (size_t)((t + 1) & 1) * (2 * Bb * Hh) + (size_t)dir * (Bb * Hh);

        // stage h (L2, bypass possibly-stale L1) into smem transposed [k][b]
        #pragma unroll
        for (int i = 0; i < 16; i++) {
            int i4 = tid + i * 128;          // 2048 float4 total
            int bb = i4 >> 7, k4 = i4 & 127;
            float4 v = __ldcg((const float4*)hread + (size_t)bb * 128 + k4);
            int k = k4 * 4;
            hs[(k + 0) * 17 + bb] = v.x;
            hs[(k + 1) * 17 + bb] = v.y;
            hs[(k + 2) * 17 + bb] = v.z;
            hs[(k + 3) * 17 + bb] = v.w;
        }
        __syncthreads();

        float ai = 0.f, af = 0.f, ag = 0.f, ao = 0.f;
        #pragma unroll 4
        for (int k4 = 0; k4 < Hh / 4; k4++) {
            float4 vi = __ldg(wi + k4);
            float4 vf = __ldg(wf + k4);
            float4 vg = __ldg(wg + k4);
            float4 vo = __ldg(wo + k4);
            int k = k4 * 4;
            float h0 = hs[(k + 0) * 17 + b];
            float h1 = hs[(k + 1) * 17 + b];
            float h2 = hs[(k + 2) * 17 + b];
            float h3 = hs[(k + 3) * 17 + b];
            ai += vi.x * h0 + vi.y * h1 + vi.z * h2 + vi.w * h3;
            af += vf.x * h0 + vf.y * h1 + vf.z * h2 + vf.w * h3;
            ag += vg.x * h0 + vg.y * h1 + vg.z * h2 + vg.w * h3;
            ao += vo.x * h0 + vo.y * h1 + vo.z * h2 + vo.w * h3;
        }

        size_t base = ((size_t)tt * Bb + b) * (size_t)H4;
        ai += __ldcs(&xg[base + 0 * Hh + j]);
        af += __ldcs(&xg[base + 1 * Hh + j]);
        ag += __ldcs(&xg[base + 2 * Hh + j]);
        ao += __ldcs(&xg[base + 3 * Hh + j]);

        float ii = 1.f / (1.f + __expf(-ai));
        float ff = 1.f / (1.f + __expf(-af));
        float gg = tanhf(ag);
        float oo = 1.f / (1.f + __expf(-ao));

        c = ff * c + ii * gg;
        float h = oo * tanhf(c);
        __stcg(&hwrite[b * Hh + j], h);
        xnext[((size_t)tt * Bb + b) * (size_t)(2 * Hh) + (size_t)dir * Hh + j] = rtf(h);

        // ---- grid sync ----
        __threadfence();          // each thread: h store visible at L2 before arrive
        __syncthreads();
        if (tid == 0) {
            atomicAdd(arr, 1u);
            unsigned target = (unsigned)(t + 1) * nb;
            unsigned v;
            do {
                asm volatile("ld.global.cg.u32 %0, [%1];" : "=r"(v) : "l"(arr) : "memory");
                if (v >= target) break;
                __nanosleep(64);
            } while (true);
        }
        __syncthreads();
    }
}

// ---------------- host launcher ----------------
extern "C" void kernel_launch(void* const* d_in, const int* in_sizes, int n_in,
                              void* d_out, int out_size) {
    const int* input = (const int*)d_in[0];
    const float* embed_w = (const float*)d_in[1];
    const float* Wih[2][2]; const float* Whh[2][2];
    const float* bih[2][2]; const float* bhh[2][2];
    int p = 2;
    for (int l = 0; l < 2; l++) {
        for (int d = 0; d < 2; d++) {
            Wih[l][d] = (const float*)d_in[p++];
            Whh[l][d] = (const float*)d_in[p++];
            bih[l][d] = (const float*)d_in[p++];
            bhh[l][d] = (const float*)d_in[p++];
        }
    }
    const float* lin_w = (const float*)d_in[18];
    const float* lin_b = (const float*)d_in[19];
    float* out = (float*)d_out;

    float *x0p, *x1p, *x2p, *xgf, *xgb, *lwp, *w0f, *w0b, *w1f, *w1b;
    cudaGetSymbolAddress((void**)&x0p, g_x0);
    cudaGetSymbolAddress((void**)&x1p, g_x1);
    cudaGetSymbolAddress((void**)&x2p, g_x2);
    cudaGetSymbolAddress((void**)&xgf, g_xg_f);
    cudaGetSymbolAddress((void**)&xgb, g_xg_b);
    cudaGetSymbolAddress((void**)&lwp, g_linw);
    cudaGetSymbolAddress((void**)&w0f, g_w0f);
    cudaGetSymbolAddress((void**)&w0b, g_w0b);
    cudaGetSymbolAddress((void**)&w1f, g_w1f);
    cudaGetSymbolAddress((void**)&w1b, g_w1b);

    cudaFuncSetAttribute(tf32_gemm, cudaFuncAttributeMaxDynamicSharedMemorySize,
                         SMEM_GEMM_TOTAL);

    // 0) round weights to tf32 (RNA) into scratch
    {
        int n4 = (Vv * 1024) / 4;
        round_copy<<<(n4 + 255) / 256, 256>>>(lin_w, lwp, n4);
        n4 = (H4 * Ee) / 4;
        round_copy<<<(n4 + 255) / 256, 256>>>(Wih[0][0], w0f, n4);
        round_copy<<<(n4 + 255) / 256, 256>>>(Wih[0][1], w0b, n4);
        n4 = (H4 * 1024) / 4;
        round_copy<<<(n4 + 255) / 256, 256>>>(Wih[1][0], w1f, n4);
        round_copy<<<(n4 + 255) / 256, 256>>>(Wih[1][1], w1b, n4);
    }

    // 1) embedding (rounded)
    embed_kernel<<<MROWS, 128>>>(input, embed_w);

    const float* xin = x0p;
    float* xouts[2] = {x1p, x2p};
    const float* wih_r[2][2] = {{w0f, w0b}, {w1f, w1b}};
    int kdims[2] = {Ee, 2 * Hh};

    for (int l = 0; l < 2; l++) {
        int K = kdims[l];
        dim3 ggrid(MROWS / 128, H4 / 128);   // (16, 16)
        tf32_gemm<<<ggrid, 256, SMEM_GEMM_TOTAL>>>(xin, wih_r[l][0], bih[l][0],
                                                   bhh[l][0], xgf, MROWS, H4, K, 0);
        tf32_gemm<<<ggrid, 256, SMEM_GEMM_TOTAL>>>(xin, wih_r[l][1], bih[l][1],
                                                   bhh[l][1], xgb, MROWS, H4, K, 0);
        zero_state<<<64, 256>>>();
        lstm_scan<<<128, 128>>>(xgf, xgb, Whh[l][0], Whh[l][1], xouts[l]);
        xin = xouts[l];
    }

    // 3) vocab projection (coalesced [B,V,S] scatter)
    dim3 ogrid(MROWS / 128, Vv / 128);       // m fastest -> lin_w L2 reuse
    tf32_gemm<<<ogrid, 256, SMEM_GEMM_TOTAL>>>(x2p, lwp, lin_b, nullptr,
                                               out, MROWS, Vv, 2 * Hh, 1);
}

// round 11
// speedup vs baseline: 1.2911x; 1.1125x over previous
#include <cuda_runtime.h>
#include <cuda_fp16.h>
#include <cstdint>

// Problem dims
#define Vv 32000
#define Ee 512
#define Hh 512
#define Bb 16
#define Ss 128
#define H4 (4*Hh)       // 2048
#define MROWS (Ss*Bb)   // 2048

// -------- device scratch (no allocation allowed) --------
__device__ __half g_x0h[MROWS * Ee];          // embed out (half)   2MB
__device__ __half g_x1h[MROWS * 2 * Hh];      // layer0 out (half)  4MB
__device__ __half g_x2h[MROWS * 2 * Hh];      // layer1 out (half)  4MB
__device__ float  g_xg_f[MROWS * H4];         // 16MB
__device__ float  g_xg_b[MROWS * H4];         // 16MB
__device__ float  g_h[2 * 2 * Bb * Hh];       // [parity][dir][b*H]
__device__ unsigned g_arrive;
// half weight copies
__device__ __half g_linwh[(size_t)Vv * 1024]; // 65MB
__device__ __half g_w0fh[H4 * Ee];
__device__ __half g_w0bh[H4 * Ee];
__device__ __half g_w1fh[H4 * 1024];
__device__ __half g_w1bh[H4 * 1024];

// ---------------- helpers ----------------
__device__ __forceinline__ uint32_t smem_u32(const void* p) {
    return (uint32_t)__cvta_generic_to_shared(p);
}
__device__ __forceinline__ void cp16(uint32_t dst, const void* src) {
    asm volatile("cp.async.cg.shared.global [%0], [%1], 16;" :: "r"(dst), "l"(src));
}
__device__ __forceinline__ void ldsm_x4(uint32_t* r, uint32_t addr) {
    asm volatile("ldmatrix.sync.aligned.m8n8.x4.shared.b16 {%0,%1,%2,%3}, [%4];"
                 : "=r"(r[0]), "=r"(r[1]), "=r"(r[2]), "=r"(r[3]) : "r"(addr));
}
__device__ __forceinline__ void ldsm_x2(uint32_t* r, uint32_t addr) {
    asm volatile("ldmatrix.sync.aligned.m8n8.x2.shared.b16 {%0,%1}, [%2];"
                 : "=r"(r[0]), "=r"(r[1]) : "r"(addr));
}
__device__ __forceinline__ void mma_f16(float* c, const uint32_t* a, const uint32_t* b) {
    asm volatile(
        "mma.sync.aligned.m16n8k16.row.col.f32.f16.f16.f32 "
        "{%0,%1,%2,%3}, {%4,%5,%6,%7}, {%8,%9}, {%0,%1,%2,%3};"
        : "+f"(c[0]), "+f"(c[1]), "+f"(c[2]), "+f"(c[3])
        : "r"(a[0]), "r"(a[1]), "r"(a[2]), "r"(a[3]), "r"(b[0]), "r"(b[1]));
}

// ---------------- small kernels ----------------
__global__ void half_copy(const float* __restrict__ s, __half* __restrict__ d, int n4) {
    int i = blockIdx.x * 256 + threadIdx.x;
    if (i < n4) {
        float4 v = ((const float4*)s)[i];
        __half2 h0 = __floats2half2_rn(v.x, v.y);
        __half2 h1 = __floats2half2_rn(v.z, v.w);
        ((__half2*)d)[2 * i]     = h0;
        ((__half2*)d)[2 * i + 1] = h1;
    }
}

__global__ void embed_kernel(const int* __restrict__ idx,
                             const float* __restrict__ ew) {
    int sb = blockIdx.x;
    int s = sb >> 4, b = sb & 15;
    int token = idx[b * Ss + s];
    const float4* src = (const float4*)(ew + (size_t)token * Ee);
    __half2* dst = (__half2*)(g_x0h + ((size_t)s * Bb + b) * Ee);
    float4 v = src[threadIdx.x];                 // 128 threads x 4 floats = 512
    dst[2 * threadIdx.x]     = __floats2half2_rn(v.x, v.y);
    dst[2 * threadIdx.x + 1] = __floats2half2_rn(v.z, v.w);
}

__global__ void zero_state() {
    int i = blockIdx.x * 256 + threadIdx.x;
    if (i < 2 * Bb * Hh) g_h[i] = 0.f;
    if (i == 0) g_arrive = 0u;
}

// ============================================================
// FP16 tensor-core GEMM (NT): C = A[M,K] . B[N,K]^T (+bias), fp32 accum
// BM=BN=128, BK=64 halves, 256 threads = 8 warps, warp tile 64x32.
// mma.sync m16n8k16 f16 -> f32. 4-stage cp.async ring, 1 sync per k-tile.
// Row pitch 72 halves (144B): 16B-aligned rows, conflict-free ldmatrix.
// mode 0: C[m*N+n] = acc + b1[n] + b2[n]
// mode 1: out[((m&15)*V + n)*S + (m>>4)] = acc + b1[n], smem-staged
// ============================================================
#define PITCH 72
#define TILEB (128 * PITCH * 2)      // 18432 bytes per tile per stage
#define SMA(st) ((st) * TILEB)
#define SMB(st) (4 * TILEB + (st) * TILEB)
#define SMEM_H (8 * TILEB)           // 147456 bytes

__global__ __launch_bounds__(256, 1)
void hgemm(const __half* __restrict__ A, const __half* __restrict__ Bw,
           const float* __restrict__ b1, const float* __restrict__ b2,
           float* __restrict__ C, int M, int N, int K, int mode) {
    extern __shared__ float smemf[];
    __half* smem = (__half*)smemf;
    const int tid = threadIdx.x;
    const int lane = tid & 31, wid = tid >> 5;
    const int gid = lane >> 2, tig = lane & 3;
    const int wm = (wid & 1) * 64;        // warp m offset
    const int wn = (wid >> 1) * 32;       // warp n offset
    const int bm = blockIdx.x * 128, bn = blockIdx.y * 128;
    uint32_t s_base = smem_u32(smem);

    // ldmatrix lane geometry (b16 canonical)
    const int q = lane >> 3, rr = lane & 7;
    const int a_row = wm + (q & 1) * 8 + rr;   // + mt*16
    const int a_chunk = (q >> 1) * 8;          // halves
    const int b_row = wn + rr;                 // + nt*8
    const int b_chunk = (q & 1) * 8;

    float acc[4][4][4];
    #pragma unroll
    for (int i = 0; i < 4; i++)
        #pragma unroll
        for (int j = 0; j < 4; j++)
            #pragma unroll
            for (int e = 0; e < 4; e++) acc[i][j][e] = 0.f;

    const int NT = K >> 6;   // K / 64

    auto load_tiles = [&](int kt, int st) {
        int kof = kt * 64;
        #pragma unroll
        for (int i = 0; i < 4; i++) {
            int id = tid + i * 256;
            int r = id >> 3, c8 = id & 7;     // 8 x 16B chunks per 64-half row
            cp16(s_base + SMA(st) + (uint32_t)((r * PITCH + c8 * 8) * 2),
                 A + (size_t)(bm + r) * K + kof + c8 * 8);
            cp16(s_base + SMB(st) + (uint32_t)((r * PITCH + c8 * 8) * 2),
                 Bw + (size_t)(bn + r) * K + kof + c8 * 8);
        }
        asm volatile("cp.async.commit_group;");
    };

    load_tiles(0, 0);
    if (NT > 1) load_tiles(1, 1);
    if (NT > 2) load_tiles(2, 2);

    for (int kt = 0; kt < NT; kt++) {
        if (kt + 3 < NT) asm volatile("cp.async.wait_group 2;");
        else             asm volatile("cp.async.wait_group 0;");
        __syncthreads();
        if (kt + 3 < NT) load_tiles(kt + 3, (kt + 3) & 3);

        const uint32_t aS = s_base + SMA(kt & 3);
        const uint32_t bS = s_base + SMB(kt & 3);

        #pragma unroll
        for (int ks = 0; ks < 4; ks++) {       // 4 x k16 = 64
            const int k0 = ks * 16;
            uint32_t af[4][4], bf[4][2];
            #pragma unroll
            for (int mt = 0; mt < 4; mt++)
                ldsm_x4(af[mt],
                        aS + (uint32_t)((((a_row + mt * 16) * PITCH) + k0 + a_chunk) * 2));
            #pragma unroll
            for (int nt = 0; nt < 4; nt++)
                ldsm_x2(bf[nt],
                        bS + (uint32_t)((((b_row + nt * 8) * PITCH) + k0 + b_chunk) * 2));
            #pragma unroll
            for (int mt = 0; mt < 4; mt++)
                #pragma unroll
                for (int nt = 0; nt < 4; nt++)
                    mma_f16(acc[mt][nt], af[mt], bf[nt]);
        }
    }

    if (mode == 0) {
        #pragma unroll
        for (int mt = 0; mt < 4; mt++) {
            int m0 = bm + wm + mt * 16 + gid;
            #pragma unroll
            for (int nt = 0; nt < 4; nt++) {
                int n = bn + wn + nt * 8 + tig * 2;
                float* a = acc[mt][nt];
                float bb0 = b1[n] + b2[n];
                float bb1 = b1[n + 1] + b2[n + 1];
                *(float2*)(C + (size_t)m0 * N + n) = make_float2(a[0] + bb0, a[1] + bb1);
                *(float2*)(C + (size_t)(m0 + 8) * N + n) = make_float2(a[2] + bb0, a[3] + bb1);
            }
        }
    } else {
        // stage C tile in smem, store float4-coalesced along s
        __syncthreads();
        float* smc = smemf;                   // [128][129] = 66KB
        #pragma unroll
        for (int mt = 0; mt < 4; mt++) {
            int ml0 = wm + mt * 16 + gid;
            #pragma unroll
            for (int nt = 0; nt < 4; nt++) {
                int nl = wn + nt * 8 + tig * 2;
                float* a = acc[mt][nt];
                smc[ml0 * 129 + nl] = a[0];
                smc[ml0 * 129 + nl + 1] = a[1];
                smc[(ml0 + 8) * 129 + nl] = a[2];
                smc[(ml0 + 8) * 129 + nl + 1] = a[3];
            }
        }
        __syncthreads();
        int s_start = bm >> 4;
        int b = tid & 15;
        #pragma unroll 1
        for (int it = 0; it < 8; it++) {
            int vl = (tid >> 4) + it * 16;
            int v = bn + vl;
            float bias = b1[v];
            float vals[8];
            #pragma unroll
            for (int sl = 0; sl < 8; sl++)
                vals[sl] = smc[(sl * 16 + b) * 129 + vl] + bias;
            size_t o = ((size_t)b * Vv + v) * Ss + s_start;
            *(float4*)(C + o)     = make_float4(vals[0], vals[1], vals[2], vals[3]);
            *(float4*)(C + o + 4) = make_float4(vals[4], vals[5], vals[6], vals[7]);
        }
    }
}

// ============================================================
// Persistent bidirectional LSTM scan: ONE launch per layer.
// c in register; h via L2 (.cg) with counter grid-sync; fp32 math.
// Output x (GEMM input for next stage) written as half.
// ============================================================
__global__ __launch_bounds__(128)
void lstm_scan(const float* __restrict__ xg_f, const float* __restrict__ xg_b,
               const float* __restrict__ Whh_f, const float* __restrict__ Whh_b,
               __half* __restrict__ xnext) {
    __shared__ float hs[Hh * 17];

    const int dir = blockIdx.x & 1;
    const int jblk = blockIdx.x >> 1;
    const int tid = threadIdx.x;
    const int b = tid & 15, jl = tid >> 4;
    const int j = jblk * 8 + jl;
    const unsigned nb = gridDim.x;

    const float* Whh = dir ? Whh_b : Whh_f;
    const float* xg = dir ? xg_b : xg_f;

    const float4* wi = (const float4*)(Whh + (size_t)(0 * Hh + j) * Hh);
    const float4* wf = (const float4*)(Whh + (size_t)(1 * Hh + j) * Hh);
    const float4* wg = (const float4*)(Whh + (size_t)(2 * Hh + j) * Hh);
    const float4* wo = (const float4*)(Whh + (size_t)(3 * Hh + j) * Hh);

    unsigned* arr = &g_arrive;
    float c = 0.f;

    for (int t = 0; t < Ss; t++) {
        int tt = dir ? (Ss - 1 - t) : t;
        const float* hread = g_h + (size_t)(t & 1) * (2 * Bb * Hh) + (size_t)dir * (Bb * Hh);
        float* hwrite = g_h + (size_t)((t + 1) & 1) * (2 * Bb * Hh) + (size_t)dir * (Bb * Hh);

        #pragma unroll
        for (int i = 0; i < 16; i++) {
            int i4 = tid + i * 128;
            int bb = i4 >> 7, k4 = i4 & 127;
            float4 v = __ldcg((const float4*)hread + (size_t)bb * 128 + k4);
            int k = k4 * 4;
            hs[(k + 0) * 17 + bb] = v.x;
            hs[(k + 1) * 17 + bb] = v.y;
            hs[(k + 2) * 17 + bb] = v.z;
            hs[(k + 3) * 17 + bb] = v.w;
        }
        __syncthreads();

        float ai = 0.f, af = 0.f, ag = 0.f, ao = 0.f;
        #pragma unroll 4
        for (int k4 = 0; k4 < Hh / 4; k4++) {
            float4 vi = __ldg(wi + k4);
            float4 vf = __ldg(wf + k4);
            float4 vg = __ldg(wg + k4);
            float4 vo = __ldg(wo + k4);
            int k = k4 * 4;
            float h0 = hs[(k + 0) * 17 + b];
            float h1 = hs[(k + 1) * 17 + b];
            float h2 = hs[(k + 2) * 17 + b];
            float h3 = hs[(k + 3) * 17 + b];
            ai += vi.x * h0 + vi.y * h1 + vi.z * h2 + vi.w * h3;
            af += vf.x * h0 + vf.y * h1 + vf.z * h2 + vf.w * h3;
            ag += vg.x * h0 + vg.y * h1 + vg.z * h2 + vg.w * h3;
            ao += vo.x * h0 + vo.y * h1 + vo.z * h2 + vo.w * h3;
        }

        size_t base = ((size_t)tt * Bb + b) * (size_t)H4;
        ai += __ldcs(&xg[base + 0 * Hh + j]);
        af += __ldcs(&xg[base + 1 * Hh + j]);
        ag += __ldcs(&xg[base + 2 * Hh + j]);
        ao += __ldcs(&xg[base + 3 * Hh + j]);

        float ii = 1.f / (1.f + __expf(-ai));
        float ff = 1.f / (1.f + __expf(-af));
        float gg = tanhf(ag);
        float oo = 1.f / (1.f + __expf(-ao));

        c = ff * c + ii * gg;
        float h = oo * tanhf(c);
        __stcg(&hwrite[b * Hh + j], h);
        xnext[((size_t)tt * Bb + b) * (size_t)(2 * Hh) + (size_t)dir * Hh + j] =
            __float2half_rn(h);

        __threadfence();
        __syncthreads();
        if (tid == 0) {
            atomicAdd(arr, 1u);
            unsigned target = (unsigned)(t + 1) * nb;
            unsigned v;
            do {
                asm volatile("ld.global.cg.u32 %0, [%1];" : "=r"(v) : "l"(arr) : "memory");
                if (v >= target) break;
                __nanosleep(64);
            } while (true);
        }
        __syncthreads();
    }
}

// ---------------- host launcher ----------------
extern "C" void kernel_launch(void* const* d_in, const int* in_sizes, int n_in,
                              void* d_out, int out_size) {
    const int* input = (const int*)d_in[0];
    const float* embed_w = (const float*)d_in[1];
    const float* Wih[2][2]; const float* Whh[2][2];
    const float* bih[2][2]; const float* bhh[2][2];
    int p = 2;
    for (int l = 0; l < 2; l++) {
        for (int d = 0; d < 2; d++) {
            Wih[l][d] = (const float*)d_in[p++];
            Whh[l][d] = (const float*)d_in[p++];
            bih[l][d] = (const float*)d_in[p++];
            bhh[l][d] = (const float*)d_in[p++];
        }
    }
    const float* lin_w = (const float*)d_in[18];
    const float* lin_b = (const float*)d_in[19];
    float* out = (float*)d_out;

    __half *x0h, *x1h, *x2h, *lwh, *w0f, *w0b, *w1f, *w1b;
    float *xgf, *xgb;
    cudaGetSymbolAddress((void**)&x0h, g_x0h);
    cudaGetSymbolAddress((void**)&x1h, g_x1h);
    cudaGetSymbolAddress((void**)&x2h, g_x2h);
    cudaGetSymbolAddress((void**)&xgf, g_xg_f);
    cudaGetSymbolAddress((void**)&xgb, g_xg_b);
    cudaGetSymbolAddress((void**)&lwh, g_linwh);
    cudaGetSymbolAddress((void**)&w0f, g_w0fh);
    cudaGetSymbolAddress((void**)&w0b, g_w0bh);
    cudaGetSymbolAddress((void**)&w1f, g_w1fh);
    cudaGetSymbolAddress((void**)&w1b, g_w1bh);

    cudaFuncSetAttribute(hgemm, cudaFuncAttributeMaxDynamicSharedMemorySize, SMEM_H);

    // 0) convert weights to half (RN)
    {
        int n4 = (Vv * 1024) / 4;
        half_copy<<<(n4 + 255) / 256, 256>>>(lin_w, lwh, n4);
        n4 = (H4 * Ee) / 4;
        half_copy<<<(n4 + 255) / 256, 256>>>(Wih[0][0], w0f, n4);
        half_copy<<<(n4 + 255) / 256, 256>>>(Wih[0][1], w0b, n4);
        n4 = (H4 * 1024) / 4;
        half_copy<<<(n4 + 255) / 256, 256>>>(Wih[1][0], w1f, n4);
        half_copy<<<(n4 + 255) / 256, 256>>>(Wih[1][1], w1b, n4);
    }

    // 1) embedding (half)
    embed_kernel<<<MROWS, 128>>>(input, embed_w);

    const __half* xin = x0h;
    __half* xouts[2] = {x1h, x2h};
    const __half* wih_h[2][2] = {{w0f, w0b}, {w1f, w1b}};
    int kdims[2] = {Ee, 2 * Hh};

    for (int l = 0; l < 2; l++) {
        int K = kdims[l];
        dim3 ggrid(MROWS / 128, H4 / 128);   // (16, 16)
        hgemm<<<ggrid, 256, SMEM_H>>>(xin, wih_h[l][0], bih[l][0], bhh[l][0],
                                      xgf, MROWS, H4, K, 0);
        hgemm<<<ggrid, 256, SMEM_H>>>(xin, wih_h[l][1], bih[l][1], bhh[l][1],
                                      xgb, MROWS, H4, K, 0);
        zero_state<<<64, 256>>>();
        lstm_scan<<<128, 128>>>(xgf, xgb, Whh[l][0], Whh[l][1], xouts[l]);
        xin = xouts[l];
    }

    // 3) vocab projection (coalesced [B,V,S] scatter)
    dim3 ogrid(MROWS / 128, Vv / 128);       // m fastest -> lin_w L2 reuse
    hgemm<<<ogrid, 256, SMEM_H>>>(x2h, lwh, lin_b, nullptr,
                                  out, MROWS, Vv, 2 * Hh, 1);
}

// round 12
// speedup vs baseline: 1.3156x; 1.0190x over previous
#include <cuda_runtime.h>
#include <cuda_fp16.h>
#include <cstdint>

// Problem dims
#define Vv 32000
#define Ee 512
#define Hh 512
#define Bb 16
#define Ss 128
#define H4 (4*Hh)       // 2048
#define MROWS (Ss*Bb)   // 2048

// -------- device scratch (no allocation allowed) --------
__device__ __half g_x0h[MROWS * Ee];          // embed out (half)   2MB
__device__ __half g_x1h[MROWS * 2 * Hh];      // layer0 out (half)  4MB
__device__ __half g_x2h[MROWS * 2 * Hh];      // layer1 out (half)  4MB
__device__ float  g_xg_f[MROWS * H4];         // 16MB
__device__ float  g_xg_b[MROWS * H4];         // 16MB
__device__ float  g_h[2 * 2 * Bb * Hh];       // [parity][dir][b*H]
__device__ unsigned g_arrive2[2];             // per-direction scan counters
// half weight copies
__device__ __half g_linwh[(size_t)Vv * 1024]; // 65MB
__device__ __half g_w0fh[H4 * Ee];
__device__ __half g_w0bh[H4 * Ee];
__device__ __half g_w1fh[H4 * 1024];
__device__ __half g_w1bh[H4 * 1024];

// ---------------- helpers ----------------
__device__ __forceinline__ uint32_t smem_u32(const void* p) {
    return (uint32_t)__cvta_generic_to_shared(p);
}
__device__ __forceinline__ void cp16(uint32_t dst, const void* src) {
    asm volatile("cp.async.cg.shared.global [%0], [%1], 16;" :: "r"(dst), "l"(src));
}
__device__ __forceinline__ void ldsm_x4(uint32_t* r, uint32_t addr) {
    asm volatile("ldmatrix.sync.aligned.m8n8.x4.shared.b16 {%0,%1,%2,%3}, [%4];"
                 : "=r"(r[0]), "=r"(r[1]), "=r"(r[2]), "=r"(r[3]) : "r"(addr));
}
__device__ __forceinline__ void ldsm_x2(uint32_t* r, uint32_t addr) {
    asm volatile("ldmatrix.sync.aligned.m8n8.x2.shared.b16 {%0,%1}, [%2];"
                 : "=r"(r[0]), "=r"(r[1]) : "r"(addr));
}
__device__ __forceinline__ void mma_f16(float* c, const uint32_t* a, const uint32_t* b) {
    asm volatile(
        "mma.sync.aligned.m16n8k16.row.col.f32.f16.f16.f32 "
        "{%0,%1,%2,%3}, {%4,%5,%6,%7}, {%8,%9}, {%0,%1,%2,%3};"
        : "+f"(c[0]), "+f"(c[1]), "+f"(c[2]), "+f"(c[3])
        : "r"(a[0]), "r"(a[1]), "r"(a[2]), "r"(a[3]), "r"(b[0]), "r"(b[1]));
}
// packed fp32x2 FMA (exact fp32, 2 FMA/instr)
#define FMA2(acc, w, h) \
    asm("fma.rn.f32x2 %0, %1, %2, %0;" : "+l"(acc) : "l"(w), "l"(h))

__device__ __forceinline__ float f2lo(unsigned long long v) {
    return __uint_as_float((unsigned)(v & 0xffffffffull));
}
__device__ __forceinline__ float f2hi(unsigned long long v) {
    return __uint_as_float((unsigned)(v >> 32));
}

// ---------------- small kernels ----------------
__global__ void zero_state() {
    int i = blockIdx.x * 256 + threadIdx.x;
    if (i < 2 * Bb * Hh) g_h[i] = 0.f;    // parity-0 slab, both dirs
    if (i < 2) g_arrive2[i] = 0u;
}

__global__ void half_copy(const float* __restrict__ s, __half* __restrict__ d, int n4) {
    int i = blockIdx.x * 256 + threadIdx.x;
    if (i < n4) {
        float4 v = ((const float4*)s)[i];
        ((__half2*)d)[2 * i]     = __floats2half2_rn(v.x, v.y);
        ((__half2*)d)[2 * i + 1] = __floats2half2_rn(v.z, v.w);
    }
}

// fused conversion of the 4 Wih weights (single launch)
__global__ void half_copy_wih(const float* __restrict__ s0, __half* __restrict__ d0,
                              const float* __restrict__ s1, __half* __restrict__ d1,
                              const float* __restrict__ s2, __half* __restrict__ d2,
                              const float* __restrict__ s3, __half* __restrict__ d3) {
    const int n01 = (H4 * Ee) / 4;      // 262144 float4
    const int n23 = (H4 * 1024) / 4;    // 524288 float4
    int i = blockIdx.x * 256 + threadIdx.x;
    const float* s; __half* d; int off;
    if (i < n01)                       { s = s0; d = d0; off = i; }
    else if (i < 2 * n01)              { s = s1; d = d1; off = i - n01; }
    else if (i < 2 * n01 + n23)        { s = s2; d = d2; off = i - 2 * n01; }
    else if (i < 2 * n01 + 2 * n23)    { s = s3; d = d3; off = i - 2 * n01 - n23; }
    else return;
    float4 v = ((const float4*)s)[off];
    ((__half2*)d)[2 * off]     = __floats2half2_rn(v.x, v.y);
    ((__half2*)d)[2 * off + 1] = __floats2half2_rn(v.z, v.w);
}

__global__ void embed_kernel(const int* __restrict__ idx,
                             const float* __restrict__ ew) {
    int sb = blockIdx.x;
    int s = sb >> 4, b = sb & 15;
    int token = idx[b * Ss + s];
    const float4* src = (const float4*)(ew + (size_t)token * Ee);
    __half2* dst = (__half2*)(g_x0h + ((size_t)s * Bb + b) * Ee);
    float4 v = src[threadIdx.x];
    dst[2 * threadIdx.x]     = __floats2half2_rn(v.x, v.y);
    dst[2 * threadIdx.x + 1] = __floats2half2_rn(v.z, v.w);
}

// ============================================================
// FP16 tensor-core GEMM (NT): C = A[M,K] . B[N,K]^T (+bias), fp32 accum
// BM=BN=128, BK=64 halves, 256 threads = 8 warps, warp tile 64x32.
// 3-stage cp.async ring, 110.5KB smem -> 2 CTAs/SM (4 warps/SMSP).
// mode 0: C[m*N+n] = acc + b1[n] + b2[n]
// mode 1: out[((m&15)*V + n)*S + (m>>4)] = acc + b1[n], smem-staged
// ============================================================
#define PITCH 72
#define TILEB (128 * PITCH * 2)      // 18432 bytes per tile per stage
#define SMA(st) ((st) * TILEB)
#define SMB(st) (3 * TILEB + (st) * TILEB)
#define SMEM_H (6 * TILEB)           // 110592 bytes

__global__ __launch_bounds__(256, 2)
void hgemm(const __half* __restrict__ A, const __half* __restrict__ Bw,
           const float* __restrict__ b1, const float* __restrict__ b2,
           float* __restrict__ C, int M, int N, int K, int mode) {
    extern __shared__ float smemf[];
    __half* smem = (__half*)smemf;
    const int tid = threadIdx.x;
    const int lane = tid & 31, wid = tid >> 5;
    const int gid = lane >> 2, tig = lane & 3;
    const int wm = (wid & 1) * 64;        // warp m offset
    const int wn = (wid >> 1) * 32;       // warp n offset
    const int bm = blockIdx.x * 128, bn = blockIdx.y * 128;
    uint32_t s_base = smem_u32(smem);

    // ldmatrix lane geometry (b16 canonical)
    const int q = lane >> 3, rr = lane & 7;
    const int a_row = wm + (q & 1) * 8 + rr;   // + mt*16
    const int a_chunk = (q >> 1) * 8;          // halves
    const int b_row = wn + rr;                 // + nt*8
    const int b_chunk = (q & 1) * 8;

    float acc[4][4][4];
    #pragma unroll
    for (int i = 0; i < 4; i++)
        #pragma unroll
        for (int j = 0; j < 4; j++)
            #pragma unroll
            for (int e = 0; e < 4; e++) acc[i][j][e] = 0.f;

    const int NT = K >> 6;   // K / 64

    auto load_tiles = [&](int kt, int st) {
        int kof = kt * 64;
        #pragma unroll
        for (int i = 0; i < 4; i++) {
            int id = tid + i * 256;
            int r = id >> 3, c8 = id & 7;
            cp16(s_base + SMA(st) + (uint32_t)((r * PITCH + c8 * 8) * 2),
                 A + (size_t)(bm + r) * K + kof + c8 * 8);
            cp16(s_base + SMB(st) + (uint32_t)((r * PITCH + c8 * 8) * 2),
                 Bw + (size_t)(bn + r) * K + kof + c8 * 8);
        }
        asm volatile("cp.async.commit_group;");
    };

    load_tiles(0, 0);
    load_tiles(1, 1);     // NT >= 8 always here

    for (int kt = 0; kt < NT; kt++) {
        if (kt + 2 < NT) asm volatile("cp.async.wait_group 1;");
        else             asm volatile("cp.async.wait_group 0;");
        __syncthreads();
        if (kt + 2 < NT) {
            int s2 = kt + 2; s2 -= (s2 >= 3) ? 3 : 0; s2 -= (s2 >= 3) ? 3 : 0;
            load_tiles(kt + 2, (kt + 2) % 3);
        }

        int cs = kt % 3;
        const uint32_t aS = s_base + SMA(cs);
        const uint32_t bS = s_base + SMB(cs);

        #pragma unroll
        for (int ks = 0; ks < 4; ks++) {
            const int k0 = ks * 16;
            uint32_t af[4][4], bf[4][2];
            #pragma unroll
            for (int mt = 0; mt < 4; mt++)
                ldsm_x4(af[mt],
                        aS + (uint32_t)((((a_row + mt * 16) * PITCH) + k0 + a_chunk) * 2));
            #pragma unroll
            for (int nt = 0; nt < 4; nt++)
                ldsm_x2(bf[nt],
                        bS + (uint32_t)((((b_row + nt * 8) * PITCH) + k0 + b_chunk) * 2));
            #pragma unroll
            for (int mt = 0; mt < 4; mt++)
                #pragma unroll
                for (int nt = 0; nt < 4; nt++)
                    mma_f16(acc[mt][nt], af[mt], bf[nt]);
        }
    }

    if (mode == 0) {
        #pragma unroll
        for (int mt = 0; mt < 4; mt++) {
            int m0 = bm + wm + mt * 16 + gid;
            #pragma unroll
            for (int nt = 0; nt < 4; nt++) {
                int n = bn + wn + nt * 8 + tig * 2;
                float* a = acc[mt][nt];
                float bb0 = b1[n] + b2[n];
                float bb1 = b1[n + 1] + b2[n + 1];
                *(float2*)(C + (size_t)m0 * N + n) = make_float2(a[0] + bb0, a[1] + bb1);
                *(float2*)(C + (size_t)(m0 + 8) * N + n) = make_float2(a[2] + bb0, a[3] + bb1);
            }
        }
    } else {
        __syncthreads();
        float* smc = smemf;                   // [128][129] = 66KB
        #pragma unroll
        for (int mt = 0; mt < 4; mt++) {
            int ml0 = wm + mt * 16 + gid;
            #pragma unroll
            for (int nt = 0; nt < 4; nt++) {
                int nl = wn + nt * 8 + tig * 2;
                float* a = acc[mt][nt];
                smc[ml0 * 129 + nl] = a[0];
                smc[ml0 * 129 + nl + 1] = a[1];
                smc[(ml0 + 8) * 129 + nl] = a[2];
                smc[(ml0 + 8) * 129 + nl + 1] = a[3];
            }
        }
        __syncthreads();
        int s_start = bm >> 4;
        int b = tid & 15;
        #pragma unroll 1
        for (int it = 0; it < 8; it++) {
            int vl = (tid >> 4) + it * 16;
            int v = bn + vl;
            float bias = b1[v];
            float vals[8];
            #pragma unroll
            for (int sl = 0; sl < 8; sl++)
                vals[sl] = smc[(sl * 16 + b) * 129 + vl] + bias;
            size_t o = ((size_t)b * Vv + v) * Ss + s_start;
            *(float4*)(C + o)     = make_float4(vals[0], vals[1], vals[2], vals[3]);
            *(float4*)(C + o + 4) = make_float4(vals[4], vals[5], vals[6], vals[7]);
        }
    }
}

// ============================================================
// Persistent bidirectional LSTM scan: ONE launch per layer.
// 128 blocks (dir = bid&1): per-direction counter sync (64 blocks each).
// fma.rn.f32x2 packed math (exact fp32, half the instructions).
// xg prefetched at iteration top; c in register; h via L2 (.cg).
// ============================================================
__global__ __launch_bounds__(128)
void lstm_scan(const float* __restrict__ xg_f, const float* __restrict__ xg_b,
               const float* __restrict__ Whh_f, const float* __restrict__ Whh_b,
               __half* __restrict__ xnext) {
    __shared__ float2 hs2[(Hh / 2) * 17];     // [k2][b], 34.8KB

    const int dir = blockIdx.x & 1;
    const int jblk = blockIdx.x >> 1;
    const int tid = threadIdx.x;
    const int b = tid & 15, jl = tid >> 4;
    const int j = jblk * 8 + jl;
    const unsigned nbd = 64;                  // blocks per direction

    const float* Whh = dir ? Whh_b : Whh_f;
    const float* xg = dir ? xg_b : xg_f;

    const ulonglong2* wi = (const ulonglong2*)(Whh + (size_t)(0 * Hh + j) * Hh);
    const ulonglong2* wf = (const ulonglong2*)(Whh + (size_t)(1 * Hh + j) * Hh);
    const ulonglong2* wg = (const ulonglong2*)(Whh + (size_t)(2 * Hh + j) * Hh);
    const ulonglong2* wo = (const ulonglong2*)(Whh + (size_t)(3 * Hh + j) * Hh);

    unsigned* arr = &g_arrive2[dir];
    float c = 0.f;

    for (int t = 0; t < Ss; t++) {
        int tt = dir ? (Ss - 1 - t) : t;
        const float* hread = g_h + (size_t)(t & 1) * (2 * Bb * Hh) + (size_t)dir * (Bb * Hh);
        float* hwrite = g_h + (size_t)((t + 1) & 1) * (2 * Bb * Hh) + (size_t)dir * (Bb * Hh);

        // prefetch xg for this step (independent of h)
        size_t base = ((size_t)tt * Bb + b) * (size_t)H4;
        float pxi = __ldcs(&xg[base + 0 * Hh + j]);
        float pxf = __ldcs(&xg[base + 1 * Hh + j]);
        float pxg = __ldcs(&xg[base + 2 * Hh + j]);
        float pxo = __ldcs(&xg[base + 3 * Hh + j]);

        // stage h (L2, bypass stale L1) into smem as float2 pairs [k2][b]
        #pragma unroll
        for (int i = 0; i < 16; i++) {
            int i4 = tid + i * 128;
            int bb = i4 >> 7, k4 = i4 & 127;
            float4 v = __ldcg((const float4*)hread + (size_t)bb * 128 + k4);
            hs2[(2 * k4 + 0) * 17 + bb] = make_float2(v.x, v.y);
            hs2[(2 * k4 + 1) * 17 + bb] = make_float2(v.z, v.w);
        }
        __syncthreads();

        unsigned long long ai2 = 0, af2 = 0, ag2 = 0, ao2 = 0;
        #pragma unroll 4
        for (int k4 = 0; k4 < Hh / 4; k4++) {
            ulonglong2 vi = wi[k4];
            ulonglong2 vf = wf[k4];
            ulonglong2 vg = wg[k4];
            ulonglong2 vo = wo[k4];
            unsigned long long h01 =
                *(const unsigned long long*)&hs2[(2 * k4 + 0) * 17 + b];
            unsigned long long h23 =
                *(const unsigned long long*)&hs2[(2 * k4 + 1) * 17 + b];
            FMA2(ai2, vi.x, h01); FMA2(ai2, vi.y, h23);
            FMA2(af2, vf.x, h01); FMA2(af2, vf.y, h23);
            FMA2(ag2, vg.x, h01); FMA2(ag2, vg.y, h23);
            FMA2(ao2, vo.x, h01); FMA2(ao2, vo.y, h23);
        }

        float ai = f2lo(ai2) + f2hi(ai2) + pxi;
        float af = f2lo(af2) + f2hi(af2) + pxf;
        float ag = f2lo(ag2) + f2hi(ag2) + pxg;
        float ao = f2lo(ao2) + f2hi(ao2) + pxo;

        float ii = 1.f / (1.f + __expf(-ai));
        float ff = 1.f / (1.f + __expf(-af));
        float gg = tanhf(ag);
        float oo = 1.f / (1.f + __expf(-ao));

        c = ff * c + ii * gg;
        float h = oo * tanhf(c);
        __stcg(&hwrite[b * Hh + j], h);
        xnext[((size_t)tt * Bb + b) * (size_t)(2 * Hh) + (size_t)dir * Hh + j] =
            __float2half_rn(h);

        // ---- per-direction grid sync ----
        __syncthreads();
        if (tid == 0) {
            __threadfence();
            atomicAdd(arr, 1u);
            unsigned target = (unsigned)(t + 1) * nbd;
            unsigned v;
            do {
                asm volatile("ld.global.cg.u32 %0, [%1];" : "=r"(v) : "l"(arr) : "memory");
                if (v >= target) break;
                __nanosleep(32);
            } while (true);
            __threadfence();
        }
        __syncthreads();
    }
}

// ---------------- host launcher ----------------
extern "C" void kernel_launch(void* const* d_in, const int* in_sizes, int n_in,
                              void* d_out, int out_size) {
    const int* input = (const int*)d_in[0];
    const float* embed_w = (const float*)d_in[1];
    const float* Wih[2][2]; const float* Whh[2][2];
    const float* bih[2][2]; const float* bhh[2][2];
    int p = 2;
    for (int l = 0; l < 2; l++) {
        for (int d = 0; d < 2; d++) {
            Wih[l][d] = (const float*)d_in[p++];
            Whh[l][d] = (const float*)d_in[p++];
            bih[l][d] = (const float*)d_in[p++];
            bhh[l][d] = (const float*)d_in[p++];
        }
    }
    const float* lin_w = (const float*)d_in[18];
    const float* lin_b = (const float*)d_in[19];
    float* out = (float*)d_out;

    __half *x0h, *x1h, *x2h, *lwh, *w0f, *w0b, *w1f, *w1b;
    float *xgf, *xgb;
    cudaGetSymbolAddress((void**)&x0h, g_x0h);
    cudaGetSymbolAddress((void**)&x1h, g_x1h);
    cudaGetSymbolAddress((void**)&x2h, g_x2h);
    cudaGetSymbolAddress((void**)&xgf, g_xg_f);
    cudaGetSymbolAddress((void**)&xgb, g_xg_b);
    cudaGetSymbolAddress((void**)&lwh, g_linwh);
    cudaGetSymbolAddress((void**)&w0f, g_w0fh);
    cudaGetSymbolAddress((void**)&w0b, g_w0bh);
    cudaGetSymbolAddress((void**)&w1f, g_w1fh);
    cudaGetSymbolAddress((void**)&w1b, g_w1bh);

    cudaFuncSetAttribute(hgemm, cudaFuncAttributeMaxDynamicSharedMemorySize, SMEM_H);

    // Launch order chosen so ncu (-s 5 -c 1) profiles launch #5 = an hgemm.
    // 0) zero state
    zero_state<<<64, 256>>>();
    // 1) lin_w -> half
    {
        int n4 = (Vv * 1024) / 4;
        half_copy<<<(n4 + 255) / 256, 256>>>(lin_w, lwh, n4);
    }
    // 2) all 4 Wih -> half (single fused launch)
    {
        int total4 = 2 * (H4 * Ee) / 4 + 2 * (H4 * 1024) / 4;   // 1.57M float4
        half_copy_wih<<<(total4 + 255) / 256, 256>>>(
            Wih[0][0], w0f, Wih[0][1], w0b, Wih[1][0], w1f, Wih[1][1], w1b);
    }
    // 3) embedding
    embed_kernel<<<MROWS, 128>>>(input, embed_w);

    const __half* xin = x0h;
    __half* xouts[2] = {x1h, x2h};
    const __half* wih_h[2][2] = {{w0f, w0b}, {w1f, w1b}};
    int kdims[2] = {Ee, 2 * Hh};

    for (int l = 0; l < 2; l++) {
        int K = kdims[l];
        dim3 ggrid(MROWS / 128, H4 / 128);   // (16, 16)
        // launches 4,5 for l=0  (5 = profiled)
        hgemm<<<ggrid, 256, SMEM_H>>>(xin, wih_h[l][0], bih[l][0], bhh[l][0],
                                      xgf, MROWS, H4, K, 0);
        hgemm<<<ggrid, 256, SMEM_H>>>(xin, wih_h[l][1], bih[l][1], bhh[l][1],
                                      xgb, MROWS, H4, K, 0);
        if (l > 0) zero_state<<<64, 256>>>();   // reset h parity-0 + counters
        lstm_scan<<<128, 128>>>(xgf, xgb, Whh[l][0], Whh[l][1], xouts[l]);
        xin = xouts[l];
    }

    // vocab projection (coalesced [B,V,S] scatter)
    dim3 ogrid(MROWS / 128, Vv / 128);       // m fastest -> lin_w L2 reuse
    hgemm<<<ogrid, 256, SMEM_H>>>(x2h, lwh, lin_b, nullptr,
                                  out, MROWS, Vv, 2 * Hh, 1);
}

// round 13
// speedup vs baseline: 1.3293x; 1.0104x over previous
#include <cuda_runtime.h>
#include <cuda_fp16.h>
#include <cstdint>

// Problem dims
#define Vv 32000
#define Ee 512
#define Hh 512
#define Bb 16
#define Ss 128
#define H4 (4*Hh)       // 2048
#define MROWS (Ss*Bb)   // 2048

// -------- device scratch (no allocation allowed) --------
__device__ __half g_x0h[MROWS * Ee];          // embed out (half)   2MB
__device__ __half g_x1h[MROWS * 2 * Hh];      // layer0 out (half)  4MB
__device__ __half g_x2h[MROWS * 2 * Hh];      // layer1 out (half)  4MB
__device__ float  g_xg_f[MROWS * H4];         // 16MB
__device__ float  g_xg_b[MROWS * H4];         // 16MB
__device__ float  g_h[2 * 2 * Bb * Hh];       // [parity][dir][b*H]
__device__ unsigned g_cnt[32];                // [dir][16] distributed scan counters
// half weight copies
__device__ __half g_linwh[(size_t)Vv * 1024]; // 65MB
__device__ __half g_w0fh[H4 * Ee];
__device__ __half g_w0bh[H4 * Ee];
__device__ __half g_w1fh[H4 * 1024];
__device__ __half g_w1bh[H4 * 1024];

// ---------------- helpers ----------------
__device__ __forceinline__ uint32_t smem_u32(const void* p) {
    return (uint32_t)__cvta_generic_to_shared(p);
}
__device__ __forceinline__ void cp16(uint32_t dst, const void* src) {
    asm volatile("cp.async.cg.shared.global [%0], [%1], 16;" :: "r"(dst), "l"(src));
}
__device__ __forceinline__ void ldsm_x4(uint32_t* r, uint32_t addr) {
    asm volatile("ldmatrix.sync.aligned.m8n8.x4.shared.b16 {%0,%1,%2,%3}, [%4];"
                 : "=r"(r[0]), "=r"(r[1]), "=r"(r[2]), "=r"(r[3]) : "r"(addr));
}
__device__ __forceinline__ void ldsm_x2(uint32_t* r, uint32_t addr) {
    asm volatile("ldmatrix.sync.aligned.m8n8.x2.shared.b16 {%0,%1}, [%2];"
                 : "=r"(r[0]), "=r"(r[1]) : "r"(addr));
}
__device__ __forceinline__ void mma_f16(float* c, const uint32_t* a, const uint32_t* b) {
    asm volatile(
        "mma.sync.aligned.m16n8k16.row.col.f32.f16.f16.f32 "
        "{%0,%1,%2,%3}, {%4,%5,%6,%7}, {%8,%9}, {%0,%1,%2,%3};"
        : "+f"(c[0]), "+f"(c[1]), "+f"(c[2]), "+f"(c[3])
        : "r"(a[0]), "r"(a[1]), "r"(a[2]), "r"(a[3]), "r"(b[0]), "r"(b[1]));
}
#define FMA2(acc, w, h) \
    asm("fma.rn.f32x2 %0, %1, %2, %0;" : "+l"(acc) : "l"(w), "l"(h))
__device__ __forceinline__ float f2lo(unsigned long long v) {
    return __uint_as_float((unsigned)(v & 0xffffffffull));
}
__device__ __forceinline__ float f2hi(unsigned long long v) {
    return __uint_as_float((unsigned)(v >> 32));
}

// ---------------- small kernels ----------------
__global__ void zero_state() {
    int i = blockIdx.x * 256 + threadIdx.x;
    if (i < 2 * Bb * Hh) g_h[i] = 0.f;    // parity-0 slab, both dirs
    if (i < 32) g_cnt[i] = 0u;
}

__global__ void half_copy(const float* __restrict__ s, __half* __restrict__ d, int n4) {
    int i = blockIdx.x * 256 + threadIdx.x;
    if (i < n4) {
        float4 v = ((const float4*)s)[i];
        ((__half2*)d)[2 * i]     = __floats2half2_rn(v.x, v.y);
        ((__half2*)d)[2 * i + 1] = __floats2half2_rn(v.z, v.w);
    }
}

__global__ void half_copy_wih(const float* __restrict__ s0, __half* __restrict__ d0,
                              const float* __restrict__ s1, __half* __restrict__ d1,
                              const float* __restrict__ s2, __half* __restrict__ d2,
                              const float* __restrict__ s3, __half* __restrict__ d3) {
    const int n01 = (H4 * Ee) / 4;
    const int n23 = (H4 * 1024) / 4;
    int i = blockIdx.x * 256 + threadIdx.x;
    const float* s; __half* d; int off;
    if (i < n01)                       { s = s0; d = d0; off = i; }
    else if (i < 2 * n01)              { s = s1; d = d1; off = i - n01; }
    else if (i < 2 * n01 + n23)        { s = s2; d = d2; off = i - 2 * n01; }
    else if (i < 2 * n01 + 2 * n23)    { s = s3; d = d3; off = i - 2 * n01 - n23; }
    else return;
    float4 v = ((const float4*)s)[off];
    ((__half2*)d)[2 * off]     = __floats2half2_rn(v.x, v.y);
    ((__half2*)d)[2 * off + 1] = __floats2half2_rn(v.z, v.w);
}

__global__ void embed_kernel(const int* __restrict__ idx,
                             const float* __restrict__ ew) {
    int sb = blockIdx.x;
    int s = sb >> 4, b = sb & 15;
    int token = idx[b * Ss + s];
    const float4* src = (const float4*)(ew + (size_t)token * Ee);
    __half2* dst = (__half2*)(g_x0h + ((size_t)s * Bb + b) * Ee);
    float4 v = src[threadIdx.x];
    dst[2 * threadIdx.x]     = __floats2half2_rn(v.x, v.y);
    dst[2 * threadIdx.x + 1] = __floats2half2_rn(v.z, v.w);
}

// ============================================================
// FP16 tensor-core GEMM body (NT): C = A[M,K].B[N,K]^T (+bias), fp32 accum
// BM=BN=128, BK=64, 8 warps, warp tile 64x32, 3-stage cp.async, 2 CTA/SM.
// ============================================================
#define PITCH 72
#define TILEB (128 * PITCH * 2)      // 18432 bytes per tile per stage
#define SMA(st) ((st) * TILEB)
#define SMB(st) (3 * TILEB + (st) * TILEB)
#define SMEM_H (6 * TILEB)           // 110592 bytes

__device__ __forceinline__
void hgemm_body(const __half* __restrict__ A, const __half* __restrict__ Bw,
                const float* __restrict__ b1, const float* __restrict__ b2,
                float* __restrict__ C, int N, int K, int mode,
                int bm, int bn, float* smemf) {
    __half* smem = (__half*)smemf;
    const int tid = threadIdx.x;
    const int lane = tid & 31, wid = tid >> 5;
    const int gid = lane >> 2, tig = lane & 3;
    const int wm = (wid & 1) * 64;
    const int wn = (wid >> 1) * 32;
    uint32_t s_base = smem_u32(smem);

    const int q = lane >> 3, rr = lane & 7;
    const int a_row = wm + (q & 1) * 8 + rr;
    const int a_chunk = (q >> 1) * 8;
    const int b_row = wn + rr;
    const int b_chunk = (q & 1) * 8;

    float acc[4][4][4];
    #pragma unroll
    for (int i = 0; i < 4; i++)
        #pragma unroll
        for (int j = 0; j < 4; j++)
            #pragma unroll
            for (int e = 0; e < 4; e++) acc[i][j][e] = 0.f;

    const int NT = K >> 6;

    auto load_tiles = [&](int kt, int st) {
        int kof = kt * 64;
        #pragma unroll
        for (int i = 0; i < 4; i++) {
            int id = tid + i * 256;
            int r = id >> 3, c8 = id & 7;
            cp16(s_base + SMA(st) + (uint32_t)((r * PITCH + c8 * 8) * 2),
                 A + (size_t)(bm + r) * K + kof + c8 * 8);
            cp16(s_base + SMB(st) + (uint32_t)((r * PITCH + c8 * 8) * 2),
                 Bw + (size_t)(bn + r) * K + kof + c8 * 8);
        }
        asm volatile("cp.async.commit_group;");
    };

    load_tiles(0, 0);
    load_tiles(1, 1);

    for (int kt = 0; kt < NT; kt++) {
        if (kt + 2 < NT) asm volatile("cp.async.wait_group 1;");
        else             asm volatile("cp.async.wait_group 0;");
        __syncthreads();
        if (kt + 2 < NT) load_tiles(kt + 2, (kt + 2) % 3);

        int cs = kt % 3;
        const uint32_t aS = s_base + SMA(cs);
        const uint32_t bS = s_base + SMB(cs);

        #pragma unroll
        for (int ks = 0; ks < 4; ks++) {
            const int k0 = ks * 16;
            uint32_t af[4][4], bf[4][2];
            #pragma unroll
            for (int mt = 0; mt < 4; mt++)
                ldsm_x4(af[mt],
                        aS + (uint32_t)((((a_row + mt * 16) * PITCH) + k0 + a_chunk) * 2));
            #pragma unroll
            for (int nt = 0; nt < 4; nt++)
                ldsm_x2(bf[nt],
                        bS + (uint32_t)((((b_row + nt * 8) * PITCH) + k0 + b_chunk) * 2));
            #pragma unroll
            for (int mt = 0; mt < 4; mt++)
                #pragma unroll
                for (int nt = 0; nt < 4; nt++)
                    mma_f16(acc[mt][nt], af[mt], bf[nt]);
        }
    }

    if (mode == 0) {
        #pragma unroll
        for (int mt = 0; mt < 4; mt++) {
            int m0 = bm + wm + mt * 16 + gid;
            #pragma unroll
            for (int nt = 0; nt < 4; nt++) {
                int n = bn + wn + nt * 8 + tig * 2;
                float* a = acc[mt][nt];
                float bb0 = b1[n] + b2[n];
                float bb1 = b1[n + 1] + b2[n + 1];
                *(float2*)(C + (size_t)m0 * N + n) = make_float2(a[0] + bb0, a[1] + bb1);
                *(float2*)(C + (size_t)(m0 + 8) * N + n) = make_float2(a[2] + bb0, a[3] + bb1);
            }
        }
    } else {
        __syncthreads();
        float* smc = smemf;                   // [128][129]
        #pragma unroll
        for (int mt = 0; mt < 4; mt++) {
            int ml0 = wm + mt * 16 + gid;
            #pragma unroll
            for (int nt = 0; nt < 4; nt++) {
                int nl = wn + nt * 8 + tig * 2;
                float* a = acc[mt][nt];
                smc[ml0 * 129 + nl] = a[0];
                smc[ml0 * 129 + nl + 1] = a[1];
                smc[(ml0 + 8) * 129 + nl] = a[2];
                smc[(ml0 + 8) * 129 + nl + 1] = a[3];
            }
        }
        __syncthreads();
        int s_start = bm >> 4;
        int b = tid & 15;
        #pragma unroll 1
        for (int it = 0; it < 8; it++) {
            int vl = (tid >> 4) + it * 16;
            int v = bn + vl;
            float bias = b1[v];
            float vals[8];
            #pragma unroll
            for (int sl = 0; sl < 8; sl++)
                vals[sl] = smc[(sl * 16 + b) * 129 + vl] + bias;
            size_t o = ((size_t)b * Vv + v) * Ss + s_start;
            *(float4*)(C + o)     = make_float4(vals[0], vals[1], vals[2], vals[3]);
            *(float4*)(C + o + 4) = make_float4(vals[4], vals[5], vals[6], vals[7]);
        }
    }
}

// fused fwd+bwd input-projection GEMM: blockIdx.z selects direction
__global__ __launch_bounds__(256, 2)
void hgemm_xg(const __half* __restrict__ A,
              const __half* __restrict__ Wf, const __half* __restrict__ Wb,
              const float* __restrict__ bihf, const float* __restrict__ bhhf,
              const float* __restrict__ bihb, const float* __restrict__ bhhb,
              float* __restrict__ Cf, float* __restrict__ Cb, int K) {
    extern __shared__ float smemf[];
    const __half* Bw = blockIdx.z ? Wb : Wf;
    const float* b1 = blockIdx.z ? bihb : bihf;
    const float* b2 = blockIdx.z ? bhhb : bhhf;
    float* C = blockIdx.z ? Cb : Cf;
    hgemm_body(A, Bw, b1, b2, C, H4, K, 0,
               blockIdx.x * 128, blockIdx.y * 128, smemf);
}

// vocab projection GEMM (scatter epilogue)
__global__ __launch_bounds__(256, 2)
void hgemm_out(const __half* __restrict__ A, const __half* __restrict__ Bw,
               const float* __restrict__ b1, float* __restrict__ C, int K) {
    extern __shared__ float smemf[];
    hgemm_body(A, Bw, b1, nullptr, C, Vv, K, 1,
               blockIdx.x * 128, blockIdx.y * 128, smemf);
}

// ============================================================
// Persistent bidirectional LSTM scan, distributed-counter sync.
// 128 blocks (dir=bid&1, 64/dir); 16 counters/dir, 4 arrivals each,
// red.global arrive + warp-collective poll.
// ============================================================
__global__ __launch_bounds__(128)
void lstm_scan(const float* __restrict__ xg_f, const float* __restrict__ xg_b,
               const float* __restrict__ Whh_f, const float* __restrict__ Whh_b,
               __half* __restrict__ xnext) {
    __shared__ float2 hs2[(Hh / 2) * 17];

    const int dir = blockIdx.x & 1;
    const int jblk = blockIdx.x >> 1;
    const int tid = threadIdx.x;
    const int b = tid & 15, jl = tid >> 4;
    const int j = jblk * 8 + jl;

    const float* Whh = dir ? Whh_b : Whh_f;
    const float* xg = dir ? xg_b : xg_f;

    const ulonglong2* wi = (const ulonglong2*)(Whh + (size_t)(0 * Hh + j) * Hh);
    const ulonglong2* wf = (const ulonglong2*)(Whh + (size_t)(1 * Hh + j) * Hh);
    const ulonglong2* wg = (const ulonglong2*)(Whh + (size_t)(2 * Hh + j) * Hh);
    const ulonglong2* wo = (const ulonglong2*)(Whh + (size_t)(3 * Hh + j) * Hh);

    unsigned* my_cnt = &g_cnt[dir * 16 + (jblk & 15)];
    const unsigned* cnt_base = &g_cnt[dir * 16];
    float c = 0.f;

    for (int t = 0; t < Ss; t++) {
        int tt = dir ? (Ss - 1 - t) : t;
        const float* hread = g_h + (size_t)(t & 1) * (2 * Bb * Hh) + (size_t)dir * (Bb * Hh);
        float* hwrite = g_h + (size_t)((t + 1) & 1) * (2 * Bb * Hh) + (size_t)dir * (Bb * Hh);

        size_t base = ((size_t)tt * Bb + b) * (size_t)H4;
        float pxi = __ldcs(&xg[base + 0 * Hh + j]);
        float pxf = __ldcs(&xg[base + 1 * Hh + j]);
        float pxg = __ldcs(&xg[base + 2 * Hh + j]);
        float pxo = __ldcs(&xg[base + 3 * Hh + j]);

        #pragma unroll
        for (int i = 0; i < 16; i++) {
            int i4 = tid + i * 128;
            int bb = i4 >> 7, k4 = i4 & 127;
            float4 v = __ldcg((const float4*)hread + (size_t)bb * 128 + k4);
            hs2[(2 * k4 + 0) * 17 + bb] = make_float2(v.x, v.y);
            hs2[(2 * k4 + 1) * 17 + bb] = make_float2(v.z, v.w);
        }
        __syncthreads();

        unsigned long long ai2 = 0, af2 = 0, ag2 = 0, ao2 = 0;
        #pragma unroll 4
        for (int k4 = 0; k4 < Hh / 4; k4++) {
            ulonglong2 vi = wi[k4];
            ulonglong2 vf = wf[k4];
            ulonglong2 vg = wg[k4];
            ulonglong2 vo = wo[k4];
            unsigned long long h01 =
                *(const unsigned long long*)&hs2[(2 * k4 + 0) * 17 + b];
            unsigned long long h23 =
                *(const unsigned long long*)&hs2[(2 * k4 + 1) * 17 + b];
            FMA2(ai2, vi.x, h01); FMA2(ai2, vi.y, h23);
            FMA2(af2, vf.x, h01); FMA2(af2, vf.y, h23);
            FMA2(ag2, vg.x, h01); FMA2(ag2, vg.y, h23);
            FMA2(ao2, vo.x, h01); FMA2(ao2, vo.y, h23);
        }

        float ai = f2lo(ai2) + f2hi(ai2) + pxi;
        float af = f2lo(af2) + f2hi(af2) + pxf;
        float ag = f2lo(ag2) + f2hi(ag2) + pxg;
        float ao = f2lo(ao2) + f2hi(ao2) + pxo;

        float ii = 1.f / (1.f + __expf(-ai));
        float ff = 1.f / (1.f + __expf(-af));
        float gg = tanhf(ag);
        float oo = 1.f / (1.f + __expf(-ao));

        c = ff * c + ii * gg;
        float h = oo * tanhf(c);
        __stcg(&hwrite[b * Hh + j], h);
        xnext[((size_t)tt * Bb + b) * (size_t)(2 * Hh) + (size_t)dir * Hh + j] =
            __float2half_rn(h);

        // ---- distributed grid sync (per direction) ----
        __syncthreads();
        if (tid == 0) {
            __threadfence();
            asm volatile("red.global.add.u32 [%0], %1;"
                         :: "l"(my_cnt), "r"(1u) : "memory");
        }
        if (tid < 32) {
            unsigned tgt = (unsigned)(t + 1) * 4u;   // 4 blocks per counter
            while (true) {
                unsigned v = tgt;
                if (tid < 16)
                    asm volatile("ld.global.cg.u32 %0, [%1];"
                                 : "=r"(v) : "l"(cnt_base + tid) : "memory");
                if (__all_sync(0xffffffffu, v >= tgt)) break;
                __nanosleep(32);
            }
        }
        __syncthreads();
    }
}

// ---------------- host launcher ----------------
extern "C" void kernel_launch(void* const* d_in, const int* in_sizes, int n_in,
                              void* d_out, int out_size) {
    const int* input = (const int*)d_in[0];
    const float* embed_w = (const float*)d_in[1];
    const float* Wih[2][2]; const float* Whh[2][2];
    const float* bih[2][2]; const float* bhh[2][2];
    int p = 2;
    for (int l = 0; l < 2; l++) {
        for (int d = 0; d < 2; d++) {
            Wih[l][d] = (const float*)d_in[p++];
            Whh[l][d] = (const float*)d_in[p++];
            bih[l][d] = (const float*)d_in[p++];
            bhh[l][d] = (const float*)d_in[p++];
        }
    }
    const float* lin_w = (const float*)d_in[18];
    const float* lin_b = (const float*)d_in[19];
    float* out = (float*)d_out;

    __half *x0h, *x1h, *x2h, *lwh, *w0f, *w0b, *w1f, *w1b;
    float *xgf, *xgb;
    cudaGetSymbolAddress((void**)&x0h, g_x0h);
    cudaGetSymbolAddress((void**)&x1h, g_x1h);
    cudaGetSymbolAddress((void**)&x2h, g_x2h);
    cudaGetSymbolAddress((void**)&xgf, g_xg_f);
    cudaGetSymbolAddress((void**)&xgb, g_xg_b);
    cudaGetSymbolAddress((void**)&lwh, g_linwh);
    cudaGetSymbolAddress((void**)&w0f, g_w0fh);
    cudaGetSymbolAddress((void**)&w0b, g_w0bh);
    cudaGetSymbolAddress((void**)&w1f, g_w1fh);
    cudaGetSymbolAddress((void**)&w1b, g_w1bh);

    cudaFuncSetAttribute(hgemm_xg, cudaFuncAttributeMaxDynamicSharedMemorySize, SMEM_H);
    cudaFuncSetAttribute(hgemm_out, cudaFuncAttributeMaxDynamicSharedMemorySize, SMEM_H);

    // Launch order: index 3 (the ncu-profiled launch) = hgemm_xg layer 0.
    // 0) all 4 Wih -> half
    {
        int total4 = 2 * (H4 * Ee) / 4 + 2 * (H4 * 1024) / 4;
        half_copy_wih<<<(total4 + 255) / 256, 256>>>(
            Wih[0][0], w0f, Wih[0][1], w0b, Wih[1][0], w1f, Wih[1][1], w1b);
    }
    // 1) embedding
    embed_kernel<<<MROWS, 128>>>(input, embed_w);
    // 2) lin_w -> half
    {
        int n4 = (Vv * 1024) / 4;
        half_copy<<<(n4 + 255) / 256, 256>>>(lin_w, lwh, n4);
    }

    const __half* xin = x0h;
    __half* xouts[2] = {x1h, x2h};
    const __half* wf_h[2] = {w0f, w1f};
    const __half* wb_h[2] = {w0b, w1b};
    int kdims[2] = {Ee, 2 * Hh};

    for (int l = 0; l < 2; l++) {
        int K = kdims[l];
        dim3 ggrid(MROWS / 128, H4 / 128, 2);    // 512 CTAs, fwd+bwd fused
        // launch index 3 (l=0) = profiled
        hgemm_xg<<<ggrid, 256, SMEM_H>>>(xin, wf_h[l], wb_h[l],
                                         bih[l][0], bhh[l][0], bih[l][1], bhh[l][1],
                                         xgf, xgb, K);
        zero_state<<<64, 256>>>();               // reset h parity-0 + counters
        lstm_scan<<<128, 128>>>(xgf, xgb, Whh[l][0], Whh[l][1], xouts[l]);
        xin = xouts[l];
    }

    // vocab projection (coalesced [B,V,S] scatter)
    dim3 ogrid(MROWS / 128, Vv / 128);           // m fastest -> lin_w L2 reuse
    hgemm_out<<<ogrid, 256, SMEM_H>>>(x2h, lwh, lin_b, out, 2 * Hh);
}

// round 15
// speedup vs baseline: 1.9893x; 1.4965x over previous
#include <cuda_runtime.h>
#include <cuda_fp16.h>
#include <cstdint>

// Problem dims
#define Vv 32000
#define Ee 512
#define Hh 512
#define Bb 16
#define Ss 128
#define H4 (4*Hh)       // 2048
#define MROWS (Ss*Bb)   // 2048

// -------- device scratch (no allocation allowed) --------
__device__ __half g_x0h[MROWS * Ee];          // embed out (half)   2MB
__device__ __half g_x1h[MROWS * 2 * Hh];      // layer0 out (half)  4MB
__device__ __half g_x2h[MROWS * 2 * Hh];      // layer1 out (half)  4MB
__device__ float  g_xg_f[MROWS * H4];         // 16MB
__device__ float  g_xg_b[MROWS * H4];         // 16MB
__device__ float  g_h[2 * 2 * Bb * Hh];       // [parity][dir][k*16+b] transposed
__device__ unsigned g_cnt[32 * 32];           // 32 counters, 128B apart
// half weight copies
__device__ __half g_linwh[(size_t)Vv * 1024]; // 65MB
__device__ __half g_w0fh[H4 * Ee];
__device__ __half g_w0bh[H4 * Ee];
__device__ __half g_w1fh[H4 * 1024];
__device__ __half g_w1bh[H4 * 1024];

// ---------------- helpers ----------------
__device__ __forceinline__ uint32_t smem_u32(const void* p) {
    return (uint32_t)__cvta_generic_to_shared(p);
}
__device__ __forceinline__ void cp16(uint32_t dst, const void* src) {
    asm volatile("cp.async.cg.shared.global [%0], [%1], 16;" :: "r"(dst), "l"(src));
}
__device__ __forceinline__ void ldsm_x4(uint32_t* r, uint32_t addr) {
    asm volatile("ldmatrix.sync.aligned.m8n8.x4.shared.b16 {%0,%1,%2,%3}, [%4];"
                 : "=r"(r[0]), "=r"(r[1]), "=r"(r[2]), "=r"(r[3]) : "r"(addr));
}
__device__ __forceinline__ void ldsm_x2(uint32_t* r, uint32_t addr) {
    asm volatile("ldmatrix.sync.aligned.m8n8.x2.shared.b16 {%0,%1}, [%2];"
                 : "=r"(r[0]), "=r"(r[1]) : "r"(addr));
}
__device__ __forceinline__ void mma_f16(float* c, const uint32_t* a, const uint32_t* b) {
    asm volatile(
        "mma.sync.aligned.m16n8k16.row.col.f32.f16.f16.f32 "
        "{%0,%1,%2,%3}, {%4,%5,%6,%7}, {%8,%9}, {%0,%1,%2,%3};"
        : "+f"(c[0]), "+f"(c[1]), "+f"(c[2]), "+f"(c[3])
        : "r"(a[0]), "r"(a[1]), "r"(a[2]), "r"(a[3]), "r"(b[0]), "r"(b[1]));
}
#define FMA2(acc, w, h) \
    asm("fma.rn.f32x2 %0, %1, %2, %0;" : "+l"(acc) : "l"(w), "l"(h))
__device__ __forceinline__ float f2lo(unsigned long long v) {
    return __uint_as_float((unsigned)(v & 0xffffffffull));
}
__device__ __forceinline__ float f2hi(unsigned long long v) {
    return __uint_as_float((unsigned)(v >> 32));
}

// ---------------- small kernels ----------------
// fused conversion of the 4 Wih weights + counter zeroing (single launch)
__global__ void half_copy_wih(const float* __restrict__ s0, __half* __restrict__ d0,
                              const float* __restrict__ s1, __half* __restrict__ d1,
                              const float* __restrict__ s2, __half* __restrict__ d2,
                              const float* __restrict__ s3, __half* __restrict__ d3) {
    if (blockIdx.x == 0) {
        #pragma unroll
        for (int k = 0; k < 4; k++) g_cnt[threadIdx.x + k * 256] = 0u;
    }
    const int n01 = (H4 * Ee) / 4;
    const int n23 = (H4 * 1024) / 4;
    int i = blockIdx.x * 256 + threadIdx.x;
    const float* s; __half* d; int off;
    if (i < n01)                       { s = s0; d = d0; off = i; }
    else if (i < 2 * n01)              { s = s1; d = d1; off = i - n01; }
    else if (i < 2 * n01 + n23)        { s = s2; d = d2; off = i - 2 * n01; }
    else if (i < 2 * n01 + 2 * n23)    { s = s3; d = d3; off = i - 2 * n01 - n23; }
    else return;
    float4 v = ((const float4*)s)[off];
    ((__half2*)d)[2 * off]     = __floats2half2_rn(v.x, v.y);
    ((__half2*)d)[2 * off + 1] = __floats2half2_rn(v.z, v.w);
}

__global__ void half_copy(const float* __restrict__ s, __half* __restrict__ d, int n4) {
    int i = blockIdx.x * 256 + threadIdx.x;
    if (i < n4) {
        float4 v = ((const float4*)s)[i];
        ((__half2*)d)[2 * i]     = __floats2half2_rn(v.x, v.y);
        ((__half2*)d)[2 * i + 1] = __floats2half2_rn(v.z, v.w);
    }
}

__global__ void embed_kernel(const int* __restrict__ idx,
                             const float* __restrict__ ew) {
    int sb = blockIdx.x;
    int s = sb >> 4, b = sb & 15;
    int token = idx[b * Ss + s];
    const float4* src = (const float4*)(ew + (size_t)token * Ee);
    __half2* dst = (__half2*)(g_x0h + ((size_t)s * Bb + b) * Ee);
    float4 v = src[threadIdx.x];
    dst[2 * threadIdx.x]     = __floats2half2_rn(v.x, v.y);
    dst[2 * threadIdx.x + 1] = __floats2half2_rn(v.z, v.w);
}

// ============================================================
// FP16 tensor-core GEMM body (NT): C = A[M,K].B[N,K]^T (+bias), fp32 accum
// BM=BN=128, BK=64, 8 warps, warp tile 64x32, 3-stage cp.async, 2 CTA/SM.
// ============================================================
#define PITCH 72
#define TILEB (128 * PITCH * 2)
#define SMA(st) ((st) * TILEB)
#define SMB(st) (3 * TILEB + (st) * TILEB)
#define SMEM_H (6 * TILEB)           // 110592 bytes

__device__ __forceinline__
void hgemm_body(const __half* __restrict__ A, const __half* __restrict__ Bw,
                const float* __restrict__ b1, const float* __restrict__ b2,
                float* __restrict__ C, int N, int K, int mode,
                int bm, int bn, float* smemf) {
    __half* smem = (__half*)smemf;
    const int tid = threadIdx.x;
    const int lane = tid & 31, wid = tid >> 5;
    const int gid = lane >> 2, tig = lane & 3;
    const int wm = (wid & 1) * 64;
    const int wn = (wid >> 1) * 32;
    uint32_t s_base = smem_u32(smem);

    const int q = lane >> 3, rr = lane & 7;
    const int a_row = wm + (q & 1) * 8 + rr;
    const int a_chunk = (q >> 1) * 8;
    const int b_row = wn + rr;
    const int b_chunk = (q & 1) * 8;

    float acc[4][4][4];
    #pragma unroll
    for (int i = 0; i < 4; i++)
        #pragma unroll
        for (int j = 0; j < 4; j++)
            #pragma unroll
            for (int e = 0; e < 4; e++) acc[i][j][e] = 0.f;

    const int NT = K >> 6;

    auto load_tiles = [&](int kt, int st) {
        int kof = kt * 64;
        #pragma unroll
        for (int i = 0; i < 4; i++) {
            int id = tid + i * 256;
            int r = id >> 3, c8 = id & 7;
            cp16(s_base + SMA(st) + (uint32_t)((r * PITCH + c8 * 8) * 2),
                 A + (size_t)(bm + r) * K + kof + c8 * 8);
            cp16(s_base + SMB(st) + (uint32_t)((r * PITCH + c8 * 8) * 2),
                 Bw + (size_t)(bn + r) * K + kof + c8 * 8);
        }
        asm volatile("cp.async.commit_group;");
    };

    load_tiles(0, 0);
    load_tiles(1, 1);

    for (int kt = 0; kt < NT; kt++) {
        if (kt + 2 < NT) asm volatile("cp.async.wait_group 1;");
        else             asm volatile("cp.async.wait_group 0;");
        __syncthreads();
        if (kt + 2 < NT) load_tiles(kt + 2, (kt + 2) % 3);

        int cs = kt % 3;
        const uint32_t aS = s_base + SMA(cs);
        const uint32_t bS = s_base + SMB(cs);

        #pragma unroll
        for (int ks = 0; ks < 4; ks++) {
            const int k0 = ks * 16;
            uint32_t af[4][4], bf[4][2];
            #pragma unroll
            for (int mt = 0; mt < 4; mt++)
                ldsm_x4(af[mt],
                        aS + (uint32_t)((((a_row + mt * 16) * PITCH) + k0 + a_chunk) * 2));
            #pragma unroll
            for (int nt = 0; nt < 4; nt++)
                ldsm_x2(bf[nt],
                        bS + (uint32_t)((((b_row + nt * 8) * PITCH) + k0 + b_chunk) * 2));
            #pragma unroll
            for (int mt = 0; mt < 4; mt++)
                #pragma unroll
                for (int nt = 0; nt < 4; nt++)
                    mma_f16(acc[mt][nt], af[mt], bf[nt]);
        }
    }

    if (mode == 0) {
        #pragma unroll
        for (int mt = 0; mt < 4; mt++) {
            int m0 = bm + wm + mt * 16 + gid;
            #pragma unroll
            for (int nt = 0; nt < 4; nt++) {
                int n = bn + wn + nt * 8 + tig * 2;
                float* a = acc[mt][nt];
                float bb0 = b1[n] + b2[n];
                float bb1 = b1[n + 1] + b2[n + 1];
                *(float2*)(C + (size_t)m0 * N + n) = make_float2(a[0] + bb0, a[1] + bb1);
                *(float2*)(C + (size_t)(m0 + 8) * N + n) = make_float2(a[2] + bb0, a[3] + bb1);
            }
        }
    } else {
        __syncthreads();
        float* smc = smemf;                   // [128][129]
        #pragma unroll
        for (int mt = 0; mt < 4; mt++) {
            int ml0 = wm + mt * 16 + gid;
            #pragma unroll
            for (int nt = 0; nt < 4; nt++) {
                int nl = wn + nt * 8 + tig * 2;
                float* a = acc[mt][nt];
                smc[ml0 * 129 + nl] = a[0];
                smc[ml0 * 129 + nl + 1] = a[1];
                smc[(ml0 + 8) * 129 + nl] = a[2];
                smc[(ml0 + 8) * 129 + nl + 1] = a[3];
            }
        }
        __syncthreads();
        int s_start = bm >> 4;
        int b = tid & 15;
        #pragma unroll 1
        for (int it = 0; it < 8; it++) {
            int vl = (tid >> 4) + it * 16;
            int v = bn + vl;
            float bias = b1[v];
            float vals[8];
            #pragma unroll
            for (int sl = 0; sl < 8; sl++)
                vals[sl] = smc[(sl * 16 + b) * 129 + vl] + bias;
            size_t o = ((size_t)b * Vv + v) * Ss + s_start;
            *(float4*)(C + o)     = make_float4(vals[0], vals[1], vals[2], vals[3]);
            *(float4*)(C + o + 4) = make_float4(vals[4], vals[5], vals[6], vals[7]);
        }
    }
}

__global__ __launch_bounds__(256, 2)
void hgemm_xg(const __half* __restrict__ A,
              const __half* __restrict__ Wf, const __half* __restrict__ Wb,
              const float* __restrict__ bihf, const float* __restrict__ bhhf,
              const float* __restrict__ bihb, const float* __restrict__ bhhb,
              float* __restrict__ Cf, float* __restrict__ Cb, int K) {
    extern __shared__ float smemf[];
    const __half* Bw = blockIdx.z ? Wb : Wf;
    const float* b1 = blockIdx.z ? bihb : bihf;
    const float* b2 = blockIdx.z ? bhhb : bhhf;
    float* C = blockIdx.z ? Cb : Cf;
    hgemm_body(A, Bw, b1, b2, C, H4, K, 0,
               blockIdx.x * 128, blockIdx.y * 128, smemf);
}

__global__ __launch_bounds__(256, 2)
void hgemm_out(const __half* __restrict__ A, const __half* __restrict__ Bw,
               const float* __restrict__ b1, float* __restrict__ C, int K) {
    extern __shared__ float smemf[];
    hgemm_body(A, Bw, b1, nullptr, C, Vv, K, 1,
               blockIdx.x * 128, blockIdx.y * 128, smemf);
}

// ============================================================
// Persistent bidirectional LSTM scan v3.
// 128 blocks (dir=bid&1, 64/dir), 256 threads: k-split halves + smem reduce.
// h exchanged in transposed [k*16+b] layout (coalesced store, linear load).
// xg(t+1) prefetched before the arrive; distributed spread counters with
// layered monotone targets (no resets; t=0 skips h read entirely).
// ============================================================
__global__ __launch_bounds__(256)
void lstm_scan(const float* __restrict__ xg_f, const float* __restrict__ xg_b,
               const float* __restrict__ Whh_f, const float* __restrict__ Whh_b,
               __half* __restrict__ xnext, int layer) {
    __shared__ float hsf[256 * 34];       // [k2][2b + (k&1)], pitch 34
    __shared__ float part[128 * 4];

    const int dir = blockIdx.x & 1;
    const int jblk = blockIdx.x >> 1;     // 0..63
    const int tid = threadIdx.x;
    const int half = tid >> 7;            // k-split half
    const int wt = tid & 127;
    const int b = wt & 15, jl = wt >> 4;
    const int j = jblk * 8 + jl;
    const int kbase = half * 256;

    const float* Whh = dir ? Whh_b : Whh_f;
    const float* xg = dir ? xg_b : xg_f;

    const ulonglong2* wi = (const ulonglong2*)(Whh + (size_t)(0 * Hh + j) * Hh + kbase);
    const ulonglong2* wf = (const ulonglong2*)(Whh + (size_t)(1 * Hh + j) * Hh + kbase);
    const ulonglong2* wg = (const ulonglong2*)(Whh + (size_t)(2 * Hh + j) * Hh + kbase);
    const ulonglong2* wo = (const ulonglong2*)(Whh + (size_t)(3 * Hh + j) * Hh + kbase);

    unsigned* my_cnt = &g_cnt[(dir * 16 + (jblk & 15)) * 32];
    const int k2b = kbase >> 1;
    float c = 0.f;
    float pxi = 0.f, pxf = 0.f, pxg = 0.f, pxo = 0.f;

    if (half == 0) {                       // prefetch xg(t=0)
        int tt0 = dir ? (Ss - 1) : 0;
        size_t base = ((size_t)tt0 * Bb + b) * (size_t)H4;
        pxi = __ldcs(&xg[base + 0 * Hh + j]);
        pxf = __ldcs(&xg[base + 1 * Hh + j]);
        pxg = __ldcs(&xg[base + 2 * Hh + j]);
        pxo = __ldcs(&xg[base + 3 * Hh + j]);
    }

    for (int t = 0; t < Ss; t++) {
        int tt = dir ? (Ss - 1 - t) : t;
        const float* hread = g_h + (size_t)(t & 1) * (2 * Bb * Hh) + (size_t)dir * (Bb * Hh);
        float* hwrite = g_h + (size_t)((t + 1) & 1) * (2 * Bb * Hh) + (size_t)dir * (Bb * Hh);

        if (t > 0) {
            // wait for all blocks of this direction to finish step t-1
            if (tid < 32) {
                unsigned tgt = (unsigned)(layer * Ss + t) * 4u;
                while (true) {
                    unsigned v = tgt;
                    if (tid < 16)
                        asm volatile("ld.global.cg.u32 %0, [%1];"
                                     : "=r"(v) : "l"(&g_cnt[(dir * 16 + tid) * 32])
                                     : "memory");
                    if (__all_sync(0xffffffffu, v >= tgt)) break;
                }
            }
            __syncthreads();
            // linear load of transposed h -> smem [k2][2b+(k&1)]
            const float4* h4 = (const float4*)hread;
            #pragma unroll
            for (int i = 0; i < 8; i++) {
                int idx = tid + i * 256;
                float4 v = __ldcg(h4 + idx);
                int k = idx >> 2, b0 = (idx & 3) * 4;
                int o = (k >> 1) * 34 + 2 * b0 + (k & 1);
                hsf[o] = v.x; hsf[o + 2] = v.y; hsf[o + 4] = v.z; hsf[o + 6] = v.w;
            }
        } else {
            for (int i = tid; i < 256 * 34; i += 256) hsf[i] = 0.f;
        }
        __syncthreads();

        unsigned long long ai2 = 0, af2 = 0, ag2 = 0, ao2 = 0;
        #pragma unroll 8
        for (int kk = 0; kk < 64; kk++) {
            ulonglong2 vi = wi[kk];
            ulonglong2 vf = wf[kk];
            ulonglong2 vg = wg[kk];
            ulonglong2 vo = wo[kk];
            unsigned long long h01 =
                *(const unsigned long long*)&hsf[(k2b + 2 * kk) * 34 + 2 * b];
            unsigned long long h23 =
                *(const unsigned long long*)&hsf[(k2b + 2 * kk + 1) * 34 + 2 * b];
            FMA2(ai2, vi.x, h01); FMA2(ai2, vi.y, h23);
            FMA2(af2, vf.x, h01); FMA2(af2, vf.y, h23);
            FMA2(ag2, vg.x, h01); FMA2(ag2, vg.y, h23);
            FMA2(ao2, vo.x, h01); FMA2(ao2, vo.y, h23);
        }
        float sai = f2lo(ai2) + f2hi(ai2);
        float saf = f2lo(af2) + f2hi(af2);
        float sag = f2lo(ag2) + f2hi(ag2);
        float sao = f2lo(ao2) + f2hi(ao2);

        if (half) {
            part[wt * 4 + 0] = sai; part[wt * 4 + 1] = saf;
            part[wt * 4 + 2] = sag; part[wt * 4 + 3] = sao;
        }
        __syncthreads();

        if (half == 0) {
            float ai = sai + part[wt * 4 + 0] + pxi;
            float af = saf + part[wt * 4 + 1] + pxf;
            float ag = sag + part[wt * 4 + 2] + pxg;
            float ao = sao + part[wt * 4 + 3] + pxo;

            float ii = 1.f / (1.f + __expf(-ai));
            float ff = 1.f / (1.f + __expf(-af));
            float gg = tanhf(ag);
            float oo = 1.f / (1.f + __expf(-ao));

            c = ff * c + ii * gg;
            float h = oo * tanhf(c);
            __stcg(&hwrite[j * 16 + b], h);          // coalesced transposed store
            xnext[((size_t)tt * Bb + b) * (size_t)(2 * Hh) + (size_t)dir * Hh + j] =
                __float2half_rn(h);

            if (t + 1 < Ss) {                        // prefetch xg(t+1) before arrive
                int tn = dir ? (Ss - 2 - t) : (t + 1);
                size_t basen = ((size_t)tn * Bb + b) * (size_t)H4;
                pxi = __ldcs(&xg[basen + 0 * Hh + j]);
                pxf = __ldcs(&xg[basen + 1 * Hh + j]);
                pxg = __ldcs(&xg[basen + 2 * Hh + j]);
                pxo = __ldcs(&xg[basen + 3 * Hh + j]);
            }
            __threadfence();
        }
        __syncthreads();
        if (tid == 0)
            asm volatile("red.global.add.u32 [%0], %1;"
                         :: "l"(my_cnt), "r"(1u) : "memory");
    }
}

// ---------------- host launcher ----------------
extern "C" void kernel_launch(void* const* d_in, const int* in_sizes, int n_in,
                              void* d_out, int out_size) {
    const int* input = (const int*)d_in[0];
    const float* embed_w = (const float*)d_in[1];
    const float* Wih[2][2]; const float* Whh[2][2];
    const float* bih[2][2]; const float* bhh[2][2];
    int p = 2;
    for (int l = 0; l < 2; l++) {
        for (int d = 0; d < 2; d++) {
            Wih[l][d] = (const float*)d_in[p++];
            Whh[l][d] = (const float*)d_in[p++];
            bih[l][d] = (const float*)d_in[p++];
            bhh[l][d] = (const float*)d_in[p++];
        }
    }
    const float* lin_w = (const float*)d_in[18];
    const float* lin_b = (const float*)d_in[19];
    float* out = (float*)d_out;

    __half *x0h, *x1h, *x2h, *lwh, *w0f, *w0b, *w1f, *w1b;
    float *xgf, *xgb;
    cudaGetSymbolAddress((void**)&x0h, g_x0h);
    cudaGetSymbolAddress((void**)&x1h, g_x1h);
    cudaGetSymbolAddress((void**)&x2h, g_x2h);
    cudaGetSymbolAddress((void**)&xgf, g_xg_f);
    cudaGetSymbolAddress((void**)&xgb, g_xg_b);
    cudaGetSymbolAddress((void**)&lwh, g_linwh);
    cudaGetSymbolAddress((void**)&w0f, g_w0fh);
    cudaGetSymbolAddress((void**)&w0b, g_w0bh);
    cudaGetSymbolAddress((void**)&w1f, g_w1fh);
    cudaGetSymbolAddress((void**)&w1b, g_w1bh);

    cudaFuncSetAttribute(hgemm_xg, cudaFuncAttributeMaxDynamicSharedMemorySize, SMEM_H);
    cudaFuncSetAttribute(hgemm_out, cudaFuncAttributeMaxDynamicSharedMemorySize, SMEM_H);

    // Launch order: index 3 (the ncu-profiled launch) = lstm_scan layer 0.
    // 0) Wih -> half + counter zero
    {
        int total4 = 2 * (H4 * Ee) / 4 + 2 * (H4 * 1024) / 4;
        half_copy_wih<<<(total4 + 255) / 256, 256>>>(
            Wih[0][0], w0f, Wih[0][1], w0b, Wih[1][0], w1f, Wih[1][1], w1b);
    }
    // 1) embedding
    embed_kernel<<<MROWS, 128>>>(input, embed_w);

    const __half* xin = x0h;
    __half* xouts[2] = {x1h, x2h};
    const __half* wf_h[2] = {w0f, w1f};
    const __half* wb_h[2] = {w0b, w1b};
    int kdims[2] = {Ee, 2 * Hh};

    for (int l = 0; l < 2; l++) {
        int K = kdims[l];
        dim3 ggrid(MROWS / 128, H4 / 128, 2);    // 512 CTAs, fwd+bwd fused
        hgemm_xg<<<ggrid, 256, SMEM_H>>>(xin, wf_h[l], wb_h[l],
                                         bih[l][0], bhh[l][0], bih[l][1], bhh[l][1],
                                         xgf, xgb, K);
        // launch index 3 for l=0 = PROFILED
        lstm_scan<<<128, 256>>>(xgf, xgb, Whh[l][0], Whh[l][1], xouts[l], l);
        xin = xouts[l];
    }

    // 6) lin_w -> half (needed only by hgemm_out)
    {
        int n4 = (Vv * 1024) / 4;
        half_copy<<<(n4 + 255) / 256, 256>>>(lin_w, lwh, n4);
    }
    // 7) vocab projection (coalesced [B,V,S] scatter)
    dim3 ogrid(MROWS / 128, Vv / 128);           // m fastest -> lin_w L2 reuse
    hgemm_out<<<ogrid, 256, SMEM_H>>>(x2h, lwh, lin_b, out, 2 * Hh);
}

// round 16
// speedup vs baseline: 2.9992x; 1.5077x over previous
#include <cuda_runtime.h>
#include <cuda_fp16.h>
#include <cstdint>

// Problem dims
#define Vv 32000
#define Ee 512
#define Hh 512
#define Bb 16
#define Ss 128
#define H4 (4*Hh)       // 2048
#define MROWS (Ss*Bb)   // 2048

// -------- device scratch (no allocation allowed) --------
__device__ __half g_x0h[MROWS * Ee];          // embed out (half)   2MB
__device__ __half g_x1h[MROWS * 2 * Hh];      // layer0 out (half)  4MB
__device__ __half g_x2h[MROWS * 2 * Hh];      // layer1 out (half)  4MB
__device__ float  g_xg_f[MROWS * H4];         // 16MB
__device__ float  g_xg_b[MROWS * H4];         // 16MB
__device__ float  g_h[2 * 2 * Bb * Hh];       // [parity][dir][k*16+b] transposed
__device__ unsigned g_cnt[32 * 32];           // 32 counters, 128B apart
// half weight copies
__device__ __half g_linwh[(size_t)Vv * 1024]; // 65MB
__device__ __half g_w0fh[H4 * Ee];
__device__ __half g_w0bh[H4 * Ee];
__device__ __half g_w1fh[H4 * 1024];
__device__ __half g_w1bh[H4 * 1024];

// ---------------- helpers ----------------
__device__ __forceinline__ uint32_t smem_u32(const void* p) {
    return (uint32_t)__cvta_generic_to_shared(p);
}
__device__ __forceinline__ void cp16(uint32_t dst, const void* src) {
    asm volatile("cp.async.cg.shared.global [%0], [%1], 16;" :: "r"(dst), "l"(src));
}
__device__ __forceinline__ void ldsm_x4(uint32_t* r, uint32_t addr) {
    asm volatile("ldmatrix.sync.aligned.m8n8.x4.shared.b16 {%0,%1,%2,%3}, [%4];"
                 : "=r"(r[0]), "=r"(r[1]), "=r"(r[2]), "=r"(r[3]) : "r"(addr));
}
__device__ __forceinline__ void ldsm_x2(uint32_t* r, uint32_t addr) {
    asm volatile("ldmatrix.sync.aligned.m8n8.x2.shared.b16 {%0,%1}, [%2];"
                 : "=r"(r[0]), "=r"(r[1]) : "r"(addr));
}
__device__ __forceinline__ void mma_f16(float* c, const uint32_t* a, const uint32_t* b) {
    asm volatile(
        "mma.sync.aligned.m16n8k16.row.col.f32.f16.f16.f32 "
        "{%0,%1,%2,%3}, {%4,%5,%6,%7}, {%8,%9}, {%0,%1,%2,%3};"
        : "+f"(c[0]), "+f"(c[1]), "+f"(c[2]), "+f"(c[3])
        : "r"(a[0]), "r"(a[1]), "r"(a[2]), "r"(a[3]), "r"(b[0]), "r"(b[1]));
}
#define FMA2(acc, w, h) \
    asm("fma.rn.f32x2 %0, %1, %2, %0;" : "+l"(acc) : "l"(w), "l"(h))
__device__ __forceinline__ float f2lo(unsigned long long v) {
    return __uint_as_float((unsigned)(v & 0xffffffffull));
}
__device__ __forceinline__ float f2hi(unsigned long long v) {
    return __uint_as_float((unsigned)(v >> 32));
}

// ---------------- small kernels ----------------
// fused conversion of the 4 Wih weights + counter zeroing (single launch)
__global__ void half_copy_wih(const float* __restrict__ s0, __half* __restrict__ d0,
                              const float* __restrict__ s1, __half* __restrict__ d1,
                              const float* __restrict__ s2, __half* __restrict__ d2,
                              const float* __restrict__ s3, __half* __restrict__ d3) {
    if (blockIdx.x == 0) {
        #pragma unroll
        for (int k = 0; k < 4; k++) g_cnt[threadIdx.x + k * 256] = 0u;
    }
    const int n01 = (H4 * Ee) / 4;
    const int n23 = (H4 * 1024) / 4;
    int i = blockIdx.x * 256 + threadIdx.x;
    const float* s; __half* d; int off;
    if (i < n01)                       { s = s0; d = d0; off = i; }
    else if (i < 2 * n01)              { s = s1; d = d1; off = i - n01; }
    else if (i < 2 * n01 + n23)        { s = s2; d = d2; off = i - 2 * n01; }
    else if (i < 2 * n01 + 2 * n23)    { s = s3; d = d3; off = i - 2 * n01 - n23; }
    else return;
    float4 v = ((const float4*)s)[off];
    ((__half2*)d)[2 * off]     = __floats2half2_rn(v.x, v.y);
    ((__half2*)d)[2 * off + 1] = __floats2half2_rn(v.z, v.w);
}

__global__ void half_copy(const float* __restrict__ s, __half* __restrict__ d, int n4) {
    int i = blockIdx.x * 256 + threadIdx.x;
    if (i < n4) {
        float4 v = ((const float4*)s)[i];
        ((__half2*)d)[2 * i]     = __floats2half2_rn(v.x, v.y);
        ((__half2*)d)[2 * i + 1] = __floats2half2_rn(v.z, v.w);
    }
}

__global__ void embed_kernel(const int* __restrict__ idx,
                             const float* __restrict__ ew) {
    int sb = blockIdx.x;
    int s = sb >> 4, b = sb & 15;
    int token = idx[b * Ss + s];
    const float4* src = (const float4*)(ew + (size_t)token * Ee);
    __half2* dst = (__half2*)(g_x0h + ((size_t)s * Bb + b) * Ee);
    float4 v = src[threadIdx.x];
    dst[2 * threadIdx.x]     = __floats2half2_rn(v.x, v.y);
    dst[2 * threadIdx.x + 1] = __floats2half2_rn(v.z, v.w);
}

// ============================================================
// FP16 tensor-core GEMM body (NT): C = A[M,K].B[N,K]^T (+bias), fp32 accum
// BM=BN=128, BK=64, 8 warps, warp tile 64x32, 3-stage cp.async, 2 CTA/SM.
// ============================================================
#define PITCH 72
#define TILEB (128 * PITCH * 2)
#define SMA(st) ((st) * TILEB)
#define SMB(st) (3 * TILEB + (st) * TILEB)
#define SMEM_H (6 * TILEB)           // 110592 bytes

__device__ __forceinline__
void hgemm_body(const __half* __restrict__ A, const __half* __restrict__ Bw,
                const float* __restrict__ b1, const float* __restrict__ b2,
                float* __restrict__ C, int N, int K, int mode,
                int bm, int bn, float* smemf) {
    __half* smem = (__half*)smemf;
    const int tid = threadIdx.x;
    const int lane = tid & 31, wid = tid >> 5;
    const int gid = lane >> 2, tig = lane & 3;
    const int wm = (wid & 1) * 64;
    const int wn = (wid >> 1) * 32;
    uint32_t s_base = smem_u32(smem);

    const int q = lane >> 3, rr = lane & 7;
    const int a_row = wm + (q & 1) * 8 + rr;
    const int a_chunk = (q >> 1) * 8;
    const int b_row = wn + rr;
    const int b_chunk = (q & 1) * 8;

    float acc[4][4][4];
    #pragma unroll
    for (int i = 0; i < 4; i++)
        #pragma unroll
        for (int j = 0; j < 4; j++)
            #pragma unroll
            for (int e = 0; e < 4; e++) acc[i][j][e] = 0.f;

    const int NT = K >> 6;

    auto load_tiles = [&](int kt, int st) {
        int kof = kt * 64;
        #pragma unroll
        for (int i = 0; i < 4; i++) {
            int id = tid + i * 256;
            int r = id >> 3, c8 = id & 7;
            cp16(s_base + SMA(st) + (uint32_t)((r * PITCH + c8 * 8) * 2),
                 A + (size_t)(bm + r) * K + kof + c8 * 8);
            cp16(s_base + SMB(st) + (uint32_t)((r * PITCH + c8 * 8) * 2),
                 Bw + (size_t)(bn + r) * K + kof + c8 * 8);
        }
        asm volatile("cp.async.commit_group;");
    };

    load_tiles(0, 0);
    load_tiles(1, 1);

    for (int kt = 0; kt < NT; kt++) {
        if (kt + 2 < NT) asm volatile("cp.async.wait_group 1;");
        else             asm volatile("cp.async.wait_group 0;");
        __syncthreads();
        if (kt + 2 < NT) load_tiles(kt + 2, (kt + 2) % 3);

        int cs = kt % 3;
        const uint32_t aS = s_base + SMA(cs);
        const uint32_t bS = s_base + SMB(cs);

        #pragma unroll
        for (int ks = 0; ks < 4; ks++) {
            const int k0 = ks * 16;
            uint32_t af[4][4], bf[4][2];
            #pragma unroll
            for (int mt = 0; mt < 4; mt++)
                ldsm_x4(af[mt],
                        aS + (uint32_t)((((a_row + mt * 16) * PITCH) + k0 + a_chunk) * 2));
            #pragma unroll
            for (int nt = 0; nt < 4; nt++)
                ldsm_x2(bf[nt],
                        bS + (uint32_t)((((b_row + nt * 8) * PITCH) + k0 + b_chunk) * 2));
            #pragma unroll
            for (int mt = 0; mt < 4; mt++)
                #pragma unroll
                for (int nt = 0; nt < 4; nt++)
                    mma_f16(acc[mt][nt], af[mt], bf[nt]);
        }
    }

    if (mode == 0) {
        #pragma unroll
        for (int mt = 0; mt < 4; mt++) {
            int m0 = bm + wm + mt * 16 + gid;
            #pragma unroll
            for (int nt = 0; nt < 4; nt++) {
                int n = bn + wn + nt * 8 + tig * 2;
                float* a = acc[mt][nt];
                float bb0 = b1[n] + b2[n];
                float bb1 = b1[n + 1] + b2[n + 1];
                *(float2*)(C + (size_t)m0 * N + n) = make_float2(a[0] + bb0, a[1] + bb1);
                *(float2*)(C + (size_t)(m0 + 8) * N + n) = make_float2(a[2] + bb0, a[3] + bb1);
            }
        }
    } else {
        __syncthreads();
        float* smc = smemf;                   // [128][129]
        #pragma unroll
        for (int mt = 0; mt < 4; mt++) {
            int ml0 = wm + mt * 16 + gid;
            #pragma unroll
            for (int nt = 0; nt < 4; nt++) {
                int nl = wn + nt * 8 + tig * 2;
                float* a = acc[mt][nt];
                smc[ml0 * 129 + nl] = a[0];
                smc[ml0 * 129 + nl + 1] = a[1];
                smc[(ml0 + 8) * 129 + nl] = a[2];
                smc[(ml0 + 8) * 129 + nl + 1] = a[3];
            }
        }
        __syncthreads();
        int s_start = bm >> 4;
        int b = tid & 15;
        #pragma unroll 1
        for (int it = 0; it < 8; it++) {
            int vl = (tid >> 4) + it * 16;
            int v = bn + vl;
            float bias = b1[v];
            float vals[8];
            #pragma unroll
            for (int sl = 0; sl < 8; sl++)
                vals[sl] = smc[(sl * 16 + b) * 129 + vl] + bias;
            size_t o = ((size_t)b * Vv + v) * Ss + s_start;
            *(float4*)(C + o)     = make_float4(vals[0], vals[1], vals[2], vals[3]);
            *(float4*)(C + o + 4) = make_float4(vals[4], vals[5], vals[6], vals[7]);
        }
    }
}

__global__ __launch_bounds__(256, 2)
void hgemm_xg(const __half* __restrict__ A,
              const __half* __restrict__ Wf, const __half* __restrict__ Wb,
              const float* __restrict__ bihf, const float* __restrict__ bhhf,
              const float* __restrict__ bihb, const float* __restrict__ bhhb,
              float* __restrict__ Cf, float* __restrict__ Cb, int K) {
    extern __shared__ float smemf[];
    const __half* Bw = blockIdx.z ? Wb : Wf;
    const float* b1 = blockIdx.z ? bihb : bihf;
    const float* b2 = blockIdx.z ? bhhb : bhhf;
    float* C = blockIdx.z ? Cb : Cf;
    hgemm_body(A, Bw, b1, b2, C, H4, K, 0,
               blockIdx.x * 128, blockIdx.y * 128, smemf);
}

__global__ __launch_bounds__(256, 2)
void hgemm_out(const __half* __restrict__ A, const __half* __restrict__ Bw,
               const float* __restrict__ b1, float* __restrict__ C, int K) {
    extern __shared__ float smemf[];
    hgemm_body(A, Bw, b1, nullptr, C, Vv, K, 1,
               blockIdx.x * 128, blockIdx.y * 128, smemf);
}

// ============================================================
// Persistent bidirectional LSTM scan v4.
// 128 blocks (dir=bid&1, 64/dir), 256 threads (k-split halves + smem reduce).
// Whh resident in SMEM (loaded once; 2-address broadcast reads, no L1tex).
// h staged as [k/4][b][k%4] float4 runs -> LDS.128 h loads.
// Distributed spread counters, layered monotone targets, nanosleep backoff.
// ============================================================
#define WS_ROW 129                        // float4 pitch per (gate,j) row
#define WS_F4 (32 * WS_ROW)               // 4128 float4 = 66048 B
#define HS_F (128 * 68)                   // 8704 floats = 34816 B (pitch 68/group)
#define SMEM_SCAN ((WS_F4 * 4 + HS_F + 512) * 4)   // 103936 B

__global__ __launch_bounds__(256)
void lstm_scan(const float* __restrict__ xg_f, const float* __restrict__ xg_b,
               const float* __restrict__ Whh_f, const float* __restrict__ Whh_b,
               __half* __restrict__ xnext, int layer) {
    extern __shared__ float dsm[];
    float4* ws = (float4*)dsm;                 // [g4][j8] rows, pitch WS_ROW
    float* hsf = dsm + WS_F4 * 4;              // [k/4][b][k%4], pitch 68/group
    float* part = hsf + HS_F;

    const int dir = blockIdx.x & 1;
    const int jblk = blockIdx.x >> 1;     // 0..63
    const int tid = threadIdx.x;
    const int half = tid >> 7;            // k-split half
    const int wt = tid & 127;
    const int b = wt & 15, jl = wt >> 4;
    const int j = jblk * 8 + jl;
    const int kbase = half * 256;

    const float* Whh = dir ? Whh_b : Whh_f;
    const float* xg = dir ? xg_b : xg_f;

    // ---- load Whh slice (8 j x 4 gates x 512 k) into smem, once ----
    {
        const float4* wsrc = (const float4*)Whh;
        #pragma unroll
        for (int i = 0; i < 16; i++) {
            int f = tid + i * 256;            // 0..4095
            int gj = f >> 7, pos = f & 127;
            int g = gj >> 3, jlo = gj & 7;
            ws[gj * WS_ROW + pos] = wsrc[(size_t)(g * Hh + jblk * 8 + jlo) * 128 + pos];
        }
    }

    const float4* wsi = ws + (0 * 8 + jl) * WS_ROW + (kbase >> 2);
    const float4* wsf = ws + (1 * 8 + jl) * WS_ROW + (kbase >> 2);
    const float4* wsg = ws + (2 * 8 + jl) * WS_ROW + (kbase >> 2);
    const float4* wso = ws + (3 * 8 + jl) * WS_ROW + (kbase >> 2);

    unsigned* my_cnt = &g_cnt[(dir * 16 + (jblk & 15)) * 32];
    const int kg_base = kbase >> 2;       // k-group base for this half
    float c = 0.f;
    float pxi = 0.f, pxf = 0.f, pxg = 0.f, pxo = 0.f;

    if (half == 0) {                       // prefetch xg(t=0)
        int tt0 = dir ? (Ss - 1) : 0;
        size_t base = ((size_t)tt0 * Bb + b) * (size_t)H4;
        pxi = __ldcs(&xg[base + 0 * Hh + j]);
        pxf = __ldcs(&xg[base + 1 * Hh + j]);
        pxg = __ldcs(&xg[base + 2 * Hh + j]);
        pxo = __ldcs(&xg[base + 3 * Hh + j]);
    }

    for (int t = 0; t < Ss; t++) {
        int tt = dir ? (Ss - 1 - t) : t;
        float* hwrite = g_h + (size_t)((t + 1) & 1) * (2 * Bb * Hh) + (size_t)dir * (Bb * Hh);

        if (t > 0) {
            const float* hread = g_h + (size_t)(t & 1) * (2 * Bb * Hh) + (size_t)dir * (Bb * Hh);
            // wait for all blocks of this direction to finish step t-1
            if (tid < 32) {
                unsigned tgt = (unsigned)(layer * Ss + t) * 4u;
                int spin = 0;
                while (true) {
                    unsigned v = tgt;
                    if (tid < 16)
                        asm volatile("ld.global.cg.u32 %0, [%1];"
                                     : "=r"(v) : "l"(&g_cnt[(dir * 16 + tid) * 32])
                                     : "memory");
                    if (__all_sync(0xffffffffu, v >= tgt)) break;
                    __nanosleep(spin < 4 ? 40 : 160);
                    spin++;
                }
            }
            __syncthreads();
            // linear load of transposed h -> smem [k/4][b][k%4] (pitch 68)
            const float4* h4 = (const float4*)hread;
            #pragma unroll
            for (int i = 0; i < 8; i++) {
                int idx = tid + i * 256;          // 0..2047
                float4 v = __ldcg(h4 + idx);
                int k = idx >> 2, b0 = (idx & 3) * 4;
                int o = (k >> 2) * 68 + b0 * 4 + (k & 3);
                hsf[o]      = v.x;
                hsf[o + 4]  = v.y;
                hsf[o + 8]  = v.z;
                hsf[o + 12] = v.w;
            }
        } else {
            for (int i = tid; i < HS_F; i += 256) hsf[i] = 0.f;
        }
        __syncthreads();

        unsigned long long ai2 = 0, af2 = 0, ag2 = 0, ao2 = 0;
        #pragma unroll 8
        for (int kk = 0; kk < 64; kk++) {
            float4 h4v = *(const float4*)&hsf[(kg_base + kk) * 68 + b * 4];
            unsigned long long h01 = *(const unsigned long long*)&h4v.x;
            unsigned long long h23 = *(const unsigned long long*)&h4v.z;
            float4 vi4 = wsi[kk];
            float4 vf4 = wsf[kk];
            float4 vg4 = wsg[kk];
            float4 vo4 = wso[kk];
            unsigned long long wiv0 = *(const unsigned long long*)&vi4.x;
            unsigned long long wiv1 = *(const unsigned long long*)&vi4.z;
            unsigned long long wfv0 = *(const unsigned long long*)&vf4.x;
            unsigned long long wfv1 = *(const unsigned long long*)&vf4.z;
            unsigned long long wgv0 = *(const unsigned long long*)&vg4.x;
            unsigned long long wgv1 = *(const unsigned long long*)&vg4.z;
            unsigned long long wov0 = *(const unsigned long long*)&vo4.x;
            unsigned long long wov1 = *(const unsigned long long*)&vo4.z;
            FMA2(ai2, wiv0, h01); FMA2(ai2, wiv1, h23);
            FMA2(af2, wfv0, h01); FMA2(af2, wfv1, h23);
            FMA2(ag2, wgv0, h01); FMA2(ag2, wgv1, h23);
            FMA2(ao2, wov0, h01); FMA2(ao2, wov1, h23);
        }
        float sai = f2lo(ai2) + f2hi(ai2);
        float saf = f2lo(af2) + f2hi(af2);
        float sag = f2lo(ag2) + f2hi(ag2);
        float sao = f2lo(ao2) + f2hi(ao2);

        if (half) {
            part[wt * 4 + 0] = sai; part[wt * 4 + 1] = saf;
            part[wt * 4 + 2] = sag; part[wt * 4 + 3] = sao;
        }
        __syncthreads();

        if (half == 0) {
            float ai = sai + part[wt * 4 + 0] + pxi;
            float af = saf + part[wt * 4 + 1] + pxf;
            float ag = sag + part[wt * 4 + 2] + pxg;
            float ao = sao + part[wt * 4 + 3] + pxo;

            float ii = 1.f / (1.f + __expf(-ai));
            float ff = 1.f / (1.f + __expf(-af));
            float gg = tanhf(ag);
            float oo = 1.f / (1.f + __expf(-ao));

            c = ff * c + ii * gg;
            float h = oo * tanhf(c);
            __stcg(&hwrite[j * 16 + b], h);          // coalesced transposed store
            xnext[((size_t)tt * Bb + b) * (size_t)(2 * Hh) + (size_t)dir * Hh + j] =
                __float2half_rn(h);

            if (t + 1 < Ss) {                        // prefetch xg(t+1) before arrive
                int tn = dir ? (Ss - 2 - t) : (t + 1);
                size_t basen = ((size_t)tn * Bb + b) * (size_t)H4;
                pxi = __ldcs(&xg[basen + 0 * Hh + j]);
                pxf = __ldcs(&xg[basen + 1 * Hh + j]);
                pxg = __ldcs(&xg[basen + 2 * Hh + j]);
                pxo = __ldcs(&xg[basen + 3 * Hh + j]);
            }
            __threadfence();
        }
        __syncthreads();
        if (tid == 0)
            asm volatile("red.global.add.u32 [%0], %1;"
                         :: "l"(my_cnt), "r"(1u) : "memory");
    }
}

// ---------------- host launcher ----------------
extern "C" void kernel_launch(void* const* d_in, const int* in_sizes, int n_in,
                              void* d_out, int out_size) {
    const int* input = (const int*)d_in[0];
    const float* embed_w = (const float*)d_in[1];
    const float* Wih[2][2]; const float* Whh[2][2];
    const float* bih[2][2]; const float* bhh[2][2];
    int p = 2;
    for (int l = 0; l < 2; l++) {
        for (int d = 0; d < 2; d++) {
            Wih[l][d] = (const float*)d_in[p++];
            Whh[l][d] = (const float*)d_in[p++];
            bih[l][d] = (const float*)d_in[p++];
            bhh[l][d] = (const float*)d_in[p++];
        }
    }
    const float* lin_w = (const float*)d_in[18];
    const float* lin_b = (const float*)d_in[19];
    float* out = (float*)d_out;

    __half *x0h, *x1h, *x2h, *lwh, *w0f, *w0b, *w1f, *w1b;
    float *xgf, *xgb;
    cudaGetSymbolAddress((void**)&x0h, g_x0h);
    cudaGetSymbolAddress((void**)&x1h, g_x1h);
    cudaGetSymbolAddress((void**)&x2h, g_x2h);
    cudaGetSymbolAddress((void**)&xgf, g_xg_f);
    cudaGetSymbolAddress((void**)&xgb, g_xg_b);
    cudaGetSymbolAddress((void**)&lwh, g_linwh);
    cudaGetSymbolAddress((void**)&w0f, g_w0fh);
    cudaGetSymbolAddress((void**)&w0b, g_w0bh);
    cudaGetSymbolAddress((void**)&w1f, g_w1fh);
    cudaGetSymbolAddress((void**)&w1b, g_w1bh);

    cudaFuncSetAttribute(hgemm_xg, cudaFuncAttributeMaxDynamicSharedMemorySize, SMEM_H);
    cudaFuncSetAttribute(hgemm_out, cudaFuncAttributeMaxDynamicSharedMemorySize, SMEM_H);
    cudaFuncSetAttribute(lstm_scan, cudaFuncAttributeMaxDynamicSharedMemorySize, SMEM_SCAN);

    // Launch order: index 3 (the ncu-profiled launch) = lstm_scan layer 0.
    // 0) Wih -> half + counter zero
    {
        int total4 = 2 * (H4 * Ee) / 4 + 2 * (H4 * 1024) / 4;
        half_copy_wih<<<(total4 + 255) / 256, 256>>>(
            Wih[0][0], w0f, Wih[0][1], w0b, Wih[1][0], w1f, Wih[1][1], w1b);
    }
    // 1) embedding
    embed_kernel<<<MROWS, 128>>>(input, embed_w);

    const __half* xin = x0h;
    __half* xouts[2] = {x1h, x2h};
    const __half* wf_h[2] = {w0f, w1f};
    const __half* wb_h[2] = {w0b, w1b};
    int kdims[2] = {Ee, 2 * Hh};

    for (int l = 0; l < 2; l++) {
        int K = kdims[l];
        dim3 ggrid(MROWS / 128, H4 / 128, 2);    // 512 CTAs, fwd+bwd fused
        hgemm_xg<<<ggrid, 256, SMEM_H>>>(xin, wf_h[l], wb_h[l],
                                         bih[l][0], bhh[l][0], bih[l][1], bhh[l][1],
                                         xgf, xgb, K);
        // launch index 3 for l=0 = PROFILED
        lstm_scan<<<128, 256, SMEM_SCAN>>>(xgf, xgb, Whh[l][0], Whh[l][1], xouts[l], l);
        xin = xouts[l];
    }

    // lin_w -> half (needed only by hgemm_out)
    {
        int n4 = (Vv * 1024) / 4;
        half_copy<<<(n4 + 255) / 256, 256>>>(lin_w, lwh, n4);
    }
    // vocab projection (coalesced [B,V,S] scatter)
    dim3 ogrid(MROWS / 128, Vv / 128);           // m fastest -> lin_w L2 reuse
    hgemm_out<<<ogrid, 256, SMEM_H>>>(x2h, lwh, lin_b, out, 2 * Hh);
}